// round 2
// baseline (speedup 1.0000x reference)
#include <cuda_runtime.h>
#include <math.h>

#define S 512
#define B 64
#define H 512
#define D 512
#define G3 1536   // 3*H
#define NBLK 128

// ---------------- scratch (device globals; allocation-free rule) ----------------
__device__ float g_gi0[(size_t)2 * S * B * G3];   // [dir][t][b][3H]
__device__ float g_h0[2][2][B * H];               // [parity][dir][b*H+n]
__device__ float g_h1[2][2][B * H];
__device__ unsigned g_arrive;
__device__ unsigned g_release;

// ---------------- packed f32x2 helpers ----------------
typedef unsigned long long ull;

__device__ __forceinline__ ull pk2(float x, float y) {
    ull r; asm("mov.b64 %0, {%1, %2};" : "=l"(r) : "f"(x), "f"(y)); return r;
}
__device__ __forceinline__ void upk2(ull v, float& x, float& y) {
    asm("mov.b64 {%0, %1}, %2;" : "=f"(x), "=f"(y) : "l"(v));
}
__device__ __forceinline__ void ffma2(ull& d, ull a, ull b) {
    asm("fma.rn.f32x2 %0, %1, %2, %0;" : "+l"(d) : "l"(a), "l"(b));
}
__device__ __forceinline__ float sigm(float x) { return 1.0f / (1.0f + expf(-x)); }

// ---------------- init: hidden states + barrier reset ----------------
__global__ void init_h(const float* __restrict__ enc) {
    if (blockIdx.x == 0 && threadIdx.x == 0) { g_arrive = 0; g_release = 0; }
    int idx = blockIdx.x * blockDim.x + threadIdx.x;   // 131072 total
    int layer = idx >> 16;
    int rem = idx & 65535;
    int dir = rem >> 15;
    int rem2 = rem & 32767;
    int b = rem2 >> 9;
    int n = rem2 & 511;
    float v = enc[(layer * B + b) * (2 * H) + dir * H + n];
    if (layer == 0) g_h0[0][dir][b * H + n] = v;
    else            g_h1[0][dir][b * H + n] = v;
}

// ---------------- precompute gi0 = input @ Wih0^T + bih0 (both dirs) ----------------
__global__ void gemm_gi0(const float* __restrict__ x,
                         const float* __restrict__ Wf, const float* __restrict__ Wb,
                         const float* __restrict__ bf, const float* __restrict__ bb) {
    __shared__ float As[16 * 68];
    __shared__ float Bs[16 * 68];
    int s  = blockIdx.x;
    int nb = blockIdx.y;
    int d  = blockIdx.z;
    const float* W    = d ? Wb : Wf;
    const float* bias = d ? bb : bf;

    int t = threadIdx.x;
    int lr = t >> 2;
    int lk = t & 3;
    int tx = t & 15;
    int ty = t >> 4;

    ull acc[4][2];
#pragma unroll
    for (int i = 0; i < 4; i++) { acc[i][0] = 0ull; acc[i][1] = 0ull; }

    for (int kc = 0; kc < 32; kc++) {
        __syncthreads();
        int k0 = kc * 16 + lk * 4;
        float4 av = *(const float4*)&x[((size_t)lr * S + s) * D + k0];
        As[(lk * 4 + 0) * 68 + lr] = av.x;
        As[(lk * 4 + 1) * 68 + lr] = av.y;
        As[(lk * 4 + 2) * 68 + lr] = av.z;
        As[(lk * 4 + 3) * 68 + lr] = av.w;
        float4 bv = *(const float4*)&W[(size_t)(nb * 64 + lr) * D + k0];
        Bs[(lk * 4 + 0) * 68 + lr] = bv.x;
        Bs[(lk * 4 + 1) * 68 + lr] = bv.y;
        Bs[(lk * 4 + 2) * 68 + lr] = bv.z;
        Bs[(lk * 4 + 3) * 68 + lr] = bv.w;
        __syncthreads();
#pragma unroll
        for (int kk = 0; kk < 16; kk++) {
            float4 a = *(const float4*)&As[kk * 68 + ty * 4];
            const ull* bp = (const ull*)&Bs[kk * 68 + tx * 4];
            ull b0 = bp[0], b1 = bp[1];
            ull aa;
            aa = pk2(a.x, a.x); ffma2(acc[0][0], aa, b0); ffma2(acc[0][1], aa, b1);
            aa = pk2(a.y, a.y); ffma2(acc[1][0], aa, b0); ffma2(acc[1][1], aa, b1);
            aa = pk2(a.z, a.z); ffma2(acc[2][0], aa, b0); ffma2(acc[2][1], aa, b1);
            aa = pk2(a.w, a.w); ffma2(acc[3][0], aa, b0); ffma2(acc[3][1], aa, b1);
        }
    }
    int col = nb * 64 + tx * 4;
    float4 bi4 = *(const float4*)&bias[col];
#pragma unroll
    for (int i = 0; i < 4; i++) {
        int b = ty * 4 + i;
        float o0, o1, o2, o3;
        upk2(acc[i][0], o0, o1);
        upk2(acc[i][1], o2, o3);
        float4 o = make_float4(o0 + bi4.x, o1 + bi4.y, o2 + bi4.z, o3 + bi4.w);
        *(float4*)&g_gi0[(((size_t)d * S + s) * B + b) * G3 + col] = o;
    }
}

// ---------------- grid barrier (monotonic, reset by init_h each launch) ----------------
__device__ __forceinline__ void grid_bar(unsigned target) {
    __syncthreads();
    if (threadIdx.x == 0) {
        __threadfence();
        unsigned v = atomicAdd(&g_arrive, 1u) + 1u;
        if (v == target * NBLK) {
            asm volatile("st.release.gpu.u32 [%0], %1;" :: "l"(&g_release), "r"(target) : "memory");
        } else {
            unsigned r;
            do {
                asm volatile("ld.acquire.gpu.u32 %0, [%1];" : "=r"(r) : "l"(&g_release) : "memory");
            } while (r < target);
        }
    }
    __syncthreads();
}

// ---------------- persistent recurrence kernel ----------------
// grid 128 (= 2 dir x 64 hidden-groups of 8), block 256, 1 block/SM.
// Phase p: L0 at t=p (p<S) and L1 at t=p-1 (p>=1), one grid barrier per phase.
// Both consume X = g_h0[p&1][dir]; three K=512 GEMMs fused in one smem pass.
__global__ void __launch_bounds__(256, 1)
gru_persist(const float* __restrict__ Wih_f, const float* __restrict__ Wih_b,
            const float* __restrict__ Whh_f, const float* __restrict__ Whh_b,
            const float* __restrict__ bih_f, const float* __restrict__ bih_b,
            const float* __restrict__ bhh_f, const float* __restrict__ bhh_b,
            float* __restrict__ out) {
    extern __shared__ float sm[];
    float* WS0 = sm;                 // Whh layer0: [k 0..511][n 0..23] stride 26
    float* WSI = sm + 13312;         // Wih layer1
    float* WSH = sm + 26624;         // Whh layer1
    float* XS  = sm + 39936;         // [k 0..63][m 0..63] stride 65
    float* HS  = sm + 44096;
    float* GA  = sm + 48256;         // L0 gh  [m][n] stride 26
    float* GB  = sm + 49920;         // L1 gi
    float* GC  = sm + 51584;         // L1 gh

    const int tid = threadIdx.x;
    const int bid = blockIdx.x;
    const int dir = bid >> 6;
    const int hb  = (bid & 63) * 8;

    const float* Wih  = dir ? Wih_b : Wih_f;
    const float* Whh  = dir ? Whh_b : Whh_f;
    const float* bih  = dir ? bih_b : bih_f;
    const float* bhh  = dir ? bhh_b : bhh_f;
    const float* bhh0 = bhh;
    const float* bi1  = bih + G3;
    const float* bh1  = bhh + G3;

    // ---- stage all weights once (resident for all 512 steps) ----
#pragma unroll
    for (int it = 0; it < 12; it++) {
        int fi = tid + 256 * it;           // < 3072
        int n  = fi >> 7;                  // 0..23
        int kq = fi & 127;
        int grow = (n >> 3) * H + hb + (n & 7);
        float4 v0 = *(const float4*)&Whh[(size_t)grow * H + kq * 4];
        WS0[(kq * 4 + 0) * 26 + n] = v0.x;
        WS0[(kq * 4 + 1) * 26 + n] = v0.y;
        WS0[(kq * 4 + 2) * 26 + n] = v0.z;
        WS0[(kq * 4 + 3) * 26 + n] = v0.w;
        float4 vi = *(const float4*)&Wih[(size_t)G3 * D + (size_t)grow * D + kq * 4];
        WSI[(kq * 4 + 0) * 26 + n] = vi.x;
        WSI[(kq * 4 + 1) * 26 + n] = vi.y;
        WSI[(kq * 4 + 2) * 26 + n] = vi.z;
        WSI[(kq * 4 + 3) * 26 + n] = vi.w;
        float4 vh = *(const float4*)&Whh[(size_t)G3 * H + (size_t)grow * H + kq * 4];
        WSH[(kq * 4 + 0) * 26 + n] = vh.x;
        WSH[(kq * 4 + 1) * 26 + n] = vh.y;
        WSH[(kq * 4 + 2) * 26 + n] = vh.z;
        WSH[(kq * 4 + 3) * 26 + n] = vh.w;
    }

    const int m  = tid & 63;
    const int ns = (tid >> 6) * 6;

    for (int p = 0; p <= S; p++) {
        const float* X  = g_h0[p & 1][dir];          // input to L0(p) AND x-input to L1(p-1)
        const float* Hc = g_h1[(p + 1) & 1][dir];    // h1 state consumed by L1(p-1)

        ull a0 = 0, a1 = 0, a2 = 0;   // L0 gh
        ull b0 = 0, b1 = 0, b2 = 0;   // L1 gi (x part)
        ull c0 = 0, c1 = 0, c2 = 0;   // L1 gh (h part)

        for (int kc = 0; kc < 8; kc++) {
            __syncthreads();
#pragma unroll
            for (int it = 0; it < 4; it++) {
                int fi = tid + 256 * it;       // < 1024
                int mm = fi >> 4;
                int kq = fi & 15;
                float4 vx = __ldcg((const float4*)&X[mm * H + kc * 64 + kq * 4]);
                XS[(kq * 4 + 0) * 65 + mm] = vx.x;
                XS[(kq * 4 + 1) * 65 + mm] = vx.y;
                XS[(kq * 4 + 2) * 65 + mm] = vx.z;
                XS[(kq * 4 + 3) * 65 + mm] = vx.w;
                float4 vh = __ldcg((const float4*)&Hc[mm * H + kc * 64 + kq * 4]);
                HS[(kq * 4 + 0) * 65 + mm] = vh.x;
                HS[(kq * 4 + 1) * 65 + mm] = vh.y;
                HS[(kq * 4 + 2) * 65 + mm] = vh.z;
                HS[(kq * 4 + 3) * 65 + mm] = vh.w;
            }
            __syncthreads();
#pragma unroll 16
            for (int k = 0; k < 64; k++) {
                float xv = XS[k * 65 + m];
                float hv = HS[k * 65 + m];
                ull xx = pk2(xv, xv);
                ull hh = pk2(hv, hv);
                const ull* w0 = (const ull*)&WS0[(kc * 64 + k) * 26 + ns];
                const ull* wi = (const ull*)&WSI[(kc * 64 + k) * 26 + ns];
                const ull* wh = (const ull*)&WSH[(kc * 64 + k) * 26 + ns];
                ffma2(a0, xx, w0[0]); ffma2(b0, xx, wi[0]); ffma2(c0, hh, wh[0]);
                ffma2(a1, xx, w0[1]); ffma2(b1, xx, wi[1]); ffma2(c1, hh, wh[1]);
                ffma2(a2, xx, w0[2]); ffma2(b2, xx, wi[2]); ffma2(c2, hh, wh[2]);
            }
        }
        {
            ull* ga = (ull*)&GA[m * 26 + ns];
            ga[0] = a0; ga[1] = a1; ga[2] = a2;
            ull* gb = (ull*)&GB[m * 26 + ns];
            gb[0] = b0; gb[1] = b1; gb[2] = b2;
            ull* gc = (ull*)&GC[m * 26 + ns];
            gc[0] = c0; gc[1] = c1; gc[2] = c2;
        }
        __syncthreads();

        // ---- L0 epilogue: t = p ----
        if (p < S) {
            int tt = dir ? (S - 1 - p) : p;
            const float* gi = &g_gi0[((size_t)dir * S + tt) * B * G3];
            float* Xn = g_h0[(p + 1) & 1][dir];
#pragma unroll
            for (int it = 0; it < 2; it++) {
                int idx = tid + 256 * it;         // < 512
                int mm = idx & 63;
                int j  = idx >> 6;
                int row = hb + j;
                float hr = GA[mm * 26 + j]      + bhh0[row];
                float hz = GA[mm * 26 + 8 + j]  + bhh0[H + row];
                float hn = GA[mm * 26 + 16 + j] + bhh0[2 * H + row];
                const float* gim = gi + mm * G3;
                float r  = sigm(gim[row] + hr);
                float z  = sigm(gim[H + row] + hz);
                float nn = tanhf(gim[2 * H + row] + r * hn);
                float hp = __ldcg(&X[mm * H + row]);
                Xn[mm * H + row] = (1.0f - z) * nn + z * hp;
            }
        }

        // ---- L1 epilogue: t = p-1 ----
        if (p >= 1) {
            int t1 = p - 1;
            int tt = dir ? (S - 1 - t1) : t1;
            float* Hn = g_h1[p & 1][dir];
#pragma unroll
            for (int it = 0; it < 2; it++) {
                int idx = tid + 256 * it;
                int mm = idx & 63;
                int j  = idx >> 6;
                int row = hb + j;
                float ir  = GB[mm * 26 + j]      + bi1[row];
                float iz  = GB[mm * 26 + 8 + j]  + bi1[H + row];
                float inn = GB[mm * 26 + 16 + j] + bi1[2 * H + row];
                float hr  = GC[mm * 26 + j]      + bh1[row];
                float hz  = GC[mm * 26 + 8 + j]  + bh1[H + row];
                float hn  = GC[mm * 26 + 16 + j] + bh1[2 * H + row];
                float r  = sigm(ir + hr);
                float z  = sigm(iz + hz);
                float nn = tanhf(inn + r * hn);
                float hp = __ldcg(&Hc[mm * H + row]);
                float hnew = (1.0f - z) * nn + z * hp;
                Hn[mm * H + row] = hnew;
                out[(size_t)mm * (S * 2 * H) + (size_t)tt * (2 * H) + dir * H + row] = hnew;
            }
        }

        grid_bar((unsigned)(p + 1));
    }

    // ---- final hidden state copy (h0/h1 parity S&1 == 0) ----
#pragma unroll
    for (int it = 0; it < 4; it++) {
        int idx = bid * 1024 + it * 256 + tid;    // < 131072
        int l = idx >> 16;
        int b = (idx >> 10) & 63;
        int d = (idx >> 9) & 1;
        int n = idx & 511;
        float v = l ? __ldcg(&g_h1[0][d][b * H + n]) : __ldcg(&g_h0[0][d][b * H + n]);
        out[(size_t)B * S * 2 * H + idx] = v;
    }
}

// ---------------- launch ----------------
extern "C" void kernel_launch(void* const* d_in, const int* in_sizes, int n_in,
                              void* d_out, int out_size) {
    const float* input  = (const float*)d_in[0];
    const float* enc    = (const float*)d_in[1];
    const float* Wih_f  = (const float*)d_in[2];
    const float* Whh_f  = (const float*)d_in[3];
    const float* bih_f  = (const float*)d_in[4];
    const float* bhh_f  = (const float*)d_in[5];
    const float* Wih_b  = (const float*)d_in[6];
    const float* Whh_b  = (const float*)d_in[7];
    const float* bih_b  = (const float*)d_in[8];
    const float* bhh_b  = (const float*)d_in[9];
    float* out = (float*)d_out;

    const int SMEM_P = 53248 * 4;   // 212992 B
    static int configured = 0;
    if (!configured) {
        cudaFuncSetAttribute(gru_persist, cudaFuncAttributeMaxDynamicSharedMemorySize, SMEM_P);
        configured = 1;
    }

    init_h<<<512, 256>>>(enc);
    gemm_gi0<<<dim3(S, 24, 2), 256>>>(input, Wih_f, Wih_b, bih_f, bih_b);
    gru_persist<<<NBLK, 256, SMEM_P>>>(Wih_f, Wih_b, Whh_f, Whh_b,
                                       bih_f, bih_b, bhh_f, bhh_b, out);
}

// round 3
// speedup vs baseline: 1.0138x; 1.0138x over previous
#include <cuda_runtime.h>
#include <math.h>

#define S 512
#define B 64
#define H 512
#define D 512
#define G3 1536   // 3*H
#define NBLK 128

// ---------------- scratch (device globals; allocation-free rule) ----------------
__device__ float g_gi0[(size_t)2 * S * B * G3];   // [dir][t][b][3H]
__device__ float g_h0[2][2][B * H];               // [parity][dir][b*H+n]
__device__ float g_h1[2][2][B * H];
__device__ unsigned g_arrive;
__device__ unsigned g_release;

// ---------------- packed f32x2 helpers ----------------
typedef unsigned long long ull;

__device__ __forceinline__ ull pk2(float x, float y) {
    ull r; asm("mov.b64 %0, {%1, %2};" : "=l"(r) : "f"(x), "f"(y)); return r;
}
__device__ __forceinline__ void upk2(ull v, float& x, float& y) {
    asm("mov.b64 {%0, %1}, %2;" : "=f"(x), "=f"(y) : "l"(v));
}
__device__ __forceinline__ void ffma2(ull& d, ull a, ull b) {
    asm("fma.rn.f32x2 %0, %1, %2, %0;" : "+l"(d) : "l"(a), "l"(b));
}
__device__ __forceinline__ float sigm(float x) { return 1.0f / (1.0f + expf(-x)); }

// ---------------- init: hidden states + barrier reset ----------------
__global__ void init_h(const float* __restrict__ enc) {
    if (blockIdx.x == 0 && threadIdx.x == 0) { g_arrive = 0; g_release = 0; }
    int idx = blockIdx.x * blockDim.x + threadIdx.x;   // 131072 total
    int layer = idx >> 16;
    int rem = idx & 65535;
    int dir = rem >> 15;
    int rem2 = rem & 32767;
    int b = rem2 >> 9;
    int n = rem2 & 511;
    float v = enc[(layer * B + b) * (2 * H) + dir * H + n];
    if (layer == 0) g_h0[0][dir][b * H + n] = v;
    else            g_h1[0][dir][b * H + n] = v;
}

// ---------------- precompute gi0 = input @ Wih0^T + bih0 (both dirs) ----------------
__global__ void gemm_gi0(const float* __restrict__ x,
                         const float* __restrict__ Wf, const float* __restrict__ Wb,
                         const float* __restrict__ bf, const float* __restrict__ bb) {
    __shared__ float As[16 * 68];
    __shared__ float Bs[16 * 68];
    int s  = blockIdx.x;
    int nb = blockIdx.y;
    int d  = blockIdx.z;
    const float* W    = d ? Wb : Wf;
    const float* bias = d ? bb : bf;

    int t = threadIdx.x;
    int lr = t >> 2;
    int lk = t & 3;
    int tx = t & 15;
    int ty = t >> 4;

    ull acc[4][2];
#pragma unroll
    for (int i = 0; i < 4; i++) { acc[i][0] = 0ull; acc[i][1] = 0ull; }

    for (int kc = 0; kc < 32; kc++) {
        __syncthreads();
        int k0 = kc * 16 + lk * 4;
        float4 av = *(const float4*)&x[((size_t)lr * S + s) * D + k0];
        As[(lk * 4 + 0) * 68 + lr] = av.x;
        As[(lk * 4 + 1) * 68 + lr] = av.y;
        As[(lk * 4 + 2) * 68 + lr] = av.z;
        As[(lk * 4 + 3) * 68 + lr] = av.w;
        float4 bv = *(const float4*)&W[(size_t)(nb * 64 + lr) * D + k0];
        Bs[(lk * 4 + 0) * 68 + lr] = bv.x;
        Bs[(lk * 4 + 1) * 68 + lr] = bv.y;
        Bs[(lk * 4 + 2) * 68 + lr] = bv.z;
        Bs[(lk * 4 + 3) * 68 + lr] = bv.w;
        __syncthreads();
#pragma unroll
        for (int kk = 0; kk < 16; kk++) {
            float4 a = *(const float4*)&As[kk * 68 + ty * 4];
            const ull* bp = (const ull*)&Bs[kk * 68 + tx * 4];
            ull b0 = bp[0], b1 = bp[1];
            ull aa;
            aa = pk2(a.x, a.x); ffma2(acc[0][0], aa, b0); ffma2(acc[0][1], aa, b1);
            aa = pk2(a.y, a.y); ffma2(acc[1][0], aa, b0); ffma2(acc[1][1], aa, b1);
            aa = pk2(a.z, a.z); ffma2(acc[2][0], aa, b0); ffma2(acc[2][1], aa, b1);
            aa = pk2(a.w, a.w); ffma2(acc[3][0], aa, b0); ffma2(acc[3][1], aa, b1);
        }
    }
    int col = nb * 64 + tx * 4;
    float4 bi4 = *(const float4*)&bias[col];
#pragma unroll
    for (int i = 0; i < 4; i++) {
        int b = ty * 4 + i;
        float o0, o1, o2, o3;
        upk2(acc[i][0], o0, o1);
        upk2(acc[i][1], o2, o3);
        float4 o = make_float4(o0 + bi4.x, o1 + bi4.y, o2 + bi4.z, o3 + bi4.w);
        *(float4*)&g_gi0[(((size_t)d * S + s) * B + b) * G3 + col] = o;
    }
}

// ---------------- grid barrier (monotonic, reset by init_h each launch) ----------------
__device__ __forceinline__ void grid_bar(unsigned target) {
    __syncthreads();
    if (threadIdx.x == 0) {
        __threadfence();
        unsigned v = atomicAdd(&g_arrive, 1u) + 1u;
        if (v == target * NBLK) {
            asm volatile("st.release.gpu.u32 [%0], %1;" :: "l"(&g_release), "r"(target) : "memory");
        } else {
            unsigned r;
            do {
                asm volatile("ld.acquire.gpu.u32 %0, [%1];" : "=r"(r) : "l"(&g_release) : "memory");
            } while (r < target);
        }
    }
    __syncthreads();
}

// ---------------- cp.async helpers ----------------
__device__ __forceinline__ void cp_async16(float* smem_dst, const float* gsrc) {
    unsigned saddr = (unsigned)__cvta_generic_to_shared(smem_dst);
    asm volatile("cp.async.cg.shared.global [%0], [%1], 16;" :: "r"(saddr), "l"(gsrc));
}

// ---------------- persistent recurrence kernel ----------------
// grid 128 (= 2 dir x 64 hidden-groups of 8), block 512, 1 block/SM.
// Phase p: L0 at t=p (p<S) and L1 at t=p-1 (p>=1), one grid barrier per phase.
// Thread halves split the 9 accumulator pairs: h0 -> {a0,a1,a2,b0,b1}, h1 -> {b2,c0,c1,c2}.
__global__ void __launch_bounds__(512, 1)
gru_persist(const float* __restrict__ Wih_f, const float* __restrict__ Wih_b,
            const float* __restrict__ Whh_f, const float* __restrict__ Whh_b,
            const float* __restrict__ bih_f, const float* __restrict__ bih_b,
            const float* __restrict__ bhh_f, const float* __restrict__ bhh_b,
            float* __restrict__ out) {
    extern __shared__ float sm[];
    float* WS0 = sm;                 // Whh layer0: [k 0..511][n 0..23] stride 26
    float* WSI = sm + 13312;         // Wih layer1
    float* WSH = sm + 26624;         // Whh layer1
    float* XS  = sm + 39936;         // [k 0..63][m 0..63] stride 65
    float* HS  = sm + 44096;
    float* GA  = sm + 48256;         // L0 gh  [m][n] stride 26
    float* GB  = sm + 49920;         // L1 gi
    float* GC  = sm + 51584;         // L1 gh
    float* GI0S= sm + 53248;         // gi0 prefetch [m][28]

    const int tid = threadIdx.x;
    const int bid = blockIdx.x;
    const int dir = bid >> 6;
    const int hb  = (bid & 63) * 8;

    const float* Wih  = dir ? Wih_b : Wih_f;
    const float* Whh  = dir ? Whh_b : Whh_f;
    const float* bih  = dir ? bih_b : bih_f;
    const float* bhh  = dir ? bhh_b : bhh_f;
    const float* bhh0 = bhh;
    const float* bi1  = bih + G3;
    const float* bh1  = bhh + G3;

    // ---- stage all weights once (resident for all 512 steps) ----
#pragma unroll
    for (int it = 0; it < 6; it++) {
        int fi = tid + 512 * it;           // < 3072
        int n  = fi >> 7;                  // 0..23
        int kq = fi & 127;
        int grow = (n >> 3) * H + hb + (n & 7);
        float4 v0 = *(const float4*)&Whh[(size_t)grow * H + kq * 4];
        WS0[(kq * 4 + 0) * 26 + n] = v0.x;
        WS0[(kq * 4 + 1) * 26 + n] = v0.y;
        WS0[(kq * 4 + 2) * 26 + n] = v0.z;
        WS0[(kq * 4 + 3) * 26 + n] = v0.w;
        float4 vi = *(const float4*)&Wih[(size_t)G3 * D + (size_t)grow * D + kq * 4];
        WSI[(kq * 4 + 0) * 26 + n] = vi.x;
        WSI[(kq * 4 + 1) * 26 + n] = vi.y;
        WSI[(kq * 4 + 2) * 26 + n] = vi.z;
        WSI[(kq * 4 + 3) * 26 + n] = vi.w;
        float4 vh = *(const float4*)&Whh[(size_t)G3 * H + (size_t)grow * H + kq * 4];
        WSH[(kq * 4 + 0) * 26 + n] = vh.x;
        WSH[(kq * 4 + 1) * 26 + n] = vh.y;
        WSH[(kq * 4 + 2) * 26 + n] = vh.z;
        WSH[(kq * 4 + 3) * 26 + n] = vh.w;
    }

    const int m  = tid & 63;
    const int g  = (tid >> 6) & 3;
    const int ns = g * 6;
    const int hhalf = tid >> 8;          // 0 or 1

    for (int p = 0; p <= S; p++) {
        const float* X  = g_h0[p & 1][dir];          // input to L0(p) AND x-input to L1(p-1)
        const float* Hc = g_h1[(p + 1) & 1][dir];    // h1 state consumed by L1(p-1)

        // ---- prefetch gi0 tile for this phase (used ~10us later in L0 epilogue) ----
        if (p < S) {
            int tt0 = dir ? (S - 1 - p) : p;
            const float* gi = &g_gi0[((size_t)dir * S + tt0) * B * G3];
            if (tid < 384) {
                int mm = tid / 6, r = tid % 6;
                int gate = r >> 1, half = r & 1;
                cp_async16(&GI0S[mm * 28 + gate * 8 + half * 4],
                           gi + mm * G3 + gate * H + hb + half * 4);
            }
            asm volatile("cp.async.commit_group;");
        }

        ull a0 = 0, a1 = 0, a2 = 0;   // L0 gh      (h0 half)
        ull b0 = 0, b1 = 0, b2 = 0;   // L1 gi      (b0,b1 on h0; b2 on h1)
        ull c0 = 0, c1 = 0, c2 = 0;   // L1 gh      (h1 half)

        for (int kc = 0; kc < 8; kc++) {
            __syncthreads();
#pragma unroll
            for (int it = 0; it < 2; it++) {
                int fi = tid + 512 * it;       // < 1024
                int mm = fi >> 4;
                int kq = fi & 15;
                float4 vx = __ldcg((const float4*)&X[mm * H + kc * 64 + kq * 4]);
                XS[(kq * 4 + 0) * 65 + mm] = vx.x;
                XS[(kq * 4 + 1) * 65 + mm] = vx.y;
                XS[(kq * 4 + 2) * 65 + mm] = vx.z;
                XS[(kq * 4 + 3) * 65 + mm] = vx.w;
                float4 vh = __ldcg((const float4*)&Hc[mm * H + kc * 64 + kq * 4]);
                HS[(kq * 4 + 0) * 65 + mm] = vh.x;
                HS[(kq * 4 + 1) * 65 + mm] = vh.y;
                HS[(kq * 4 + 2) * 65 + mm] = vh.z;
                HS[(kq * 4 + 3) * 65 + mm] = vh.w;
            }
            __syncthreads();
            if (hhalf == 0) {
#pragma unroll 16
                for (int k = 0; k < 64; k++) {
                    float xv = XS[k * 65 + m];
                    ull xx = pk2(xv, xv);
                    const ull* w0 = (const ull*)&WS0[(kc * 64 + k) * 26 + ns];
                    const ull* wi = (const ull*)&WSI[(kc * 64 + k) * 26 + ns];
                    ffma2(a0, xx, w0[0]);
                    ffma2(a1, xx, w0[1]);
                    ffma2(a2, xx, w0[2]);
                    ffma2(b0, xx, wi[0]);
                    ffma2(b1, xx, wi[1]);
                }
            } else {
#pragma unroll 16
                for (int k = 0; k < 64; k++) {
                    float xv = XS[k * 65 + m];
                    float hv = HS[k * 65 + m];
                    ull xx = pk2(xv, xv);
                    ull hh = pk2(hv, hv);
                    const ull* wi = (const ull*)&WSI[(kc * 64 + k) * 26 + ns];
                    const ull* wh = (const ull*)&WSH[(kc * 64 + k) * 26 + ns];
                    ffma2(b2, xx, wi[2]);
                    ffma2(c0, hh, wh[0]);
                    ffma2(c1, hh, wh[1]);
                    ffma2(c2, hh, wh[2]);
                }
            }
        }
        if (hhalf == 0) {
            ull* ga = (ull*)&GA[m * 26 + ns];
            ga[0] = a0; ga[1] = a1; ga[2] = a2;
            ull* gb = (ull*)&GB[m * 26 + ns];
            gb[0] = b0; gb[1] = b1;
        } else {
            ull* gb = (ull*)&GB[m * 26 + ns];
            gb[2] = b2;
            ull* gc = (ull*)&GC[m * 26 + ns];
            gc[0] = c0; gc[1] = c1; gc[2] = c2;
        }
        asm volatile("cp.async.wait_group 0;");
        __syncthreads();

        // ---- L0 epilogue: t = p ----
        if (p < S) {
            float* Xn = g_h0[(p + 1) & 1][dir];
            int mm = tid & 63;
            int j  = tid >> 6;                // 0..7 (512 threads exactly)
            int row = hb + j;
            float hr = GA[mm * 26 + j]      + bhh0[row];
            float hz = GA[mm * 26 + 8 + j]  + bhh0[H + row];
            float hn = GA[mm * 26 + 16 + j] + bhh0[2 * H + row];
            float r  = sigm(GI0S[mm * 28 + j] + hr);
            float z  = sigm(GI0S[mm * 28 + 8 + j] + hz);
            float nn = tanhf(GI0S[mm * 28 + 16 + j] + r * hn);
            float hp = __ldcg(&X[mm * H + row]);
            Xn[mm * H + row] = (1.0f - z) * nn + z * hp;
        }

        // ---- L1 epilogue: t = p-1 ----
        if (p >= 1) {
            int t1 = p - 1;
            int tt = dir ? (S - 1 - t1) : t1;
            float* Hn = g_h1[p & 1][dir];
            int mm = tid & 63;
            int j  = tid >> 6;
            int row = hb + j;
            float ir  = GB[mm * 26 + j]      + bi1[row];
            float iz  = GB[mm * 26 + 8 + j]  + bi1[H + row];
            float inn = GB[mm * 26 + 16 + j] + bi1[2 * H + row];
            float hr  = GC[mm * 26 + j]      + bh1[row];
            float hz  = GC[mm * 26 + 8 + j]  + bh1[H + row];
            float hn  = GC[mm * 26 + 16 + j] + bh1[2 * H + row];
            float r  = sigm(ir + hr);
            float z  = sigm(iz + hz);
            float nn = tanhf(inn + r * hn);
            float hp = __ldcg(&Hc[mm * H + row]);
            float hnew = (1.0f - z) * nn + z * hp;
            Hn[mm * H + row] = hnew;
            out[(size_t)mm * (S * 2 * H) + (size_t)tt * (2 * H) + dir * H + row] = hnew;
        }

        grid_bar((unsigned)(p + 1));
    }

    // ---- final hidden state copy (h0/h1 parity S&1 == 0) ----
#pragma unroll
    for (int it = 0; it < 2; it++) {
        int idx = bid * 1024 + it * 512 + tid;    // < 131072
        int l = idx >> 16;
        int b = (idx >> 10) & 63;
        int d = (idx >> 9) & 1;
        int n = idx & 511;
        float v = l ? __ldcg(&g_h1[0][d][b * H + n]) : __ldcg(&g_h0[0][d][b * H + n]);
        out[(size_t)B * S * 2 * H + idx] = v;
    }
}

// ---------------- launch ----------------
extern "C" void kernel_launch(void* const* d_in, const int* in_sizes, int n_in,
                              void* d_out, int out_size) {
    const float* input  = (const float*)d_in[0];
    const float* enc    = (const float*)d_in[1];
    const float* Wih_f  = (const float*)d_in[2];
    const float* Whh_f  = (const float*)d_in[3];
    const float* bih_f  = (const float*)d_in[4];
    const float* bhh_f  = (const float*)d_in[5];
    const float* Wih_b  = (const float*)d_in[6];
    const float* Whh_b  = (const float*)d_in[7];
    const float* bih_b  = (const float*)d_in[8];
    const float* bhh_b  = (const float*)d_in[9];
    float* out = (float*)d_out;

    const int SMEM_P = 55040 * 4;   // 220160 B
    static int configured = 0;
    if (!configured) {
        cudaFuncSetAttribute(gru_persist, cudaFuncAttributeMaxDynamicSharedMemorySize, SMEM_P);
        configured = 1;
    }

    init_h<<<512, 256>>>(enc);
    gemm_gi0<<<dim3(S, 24, 2), 256>>>(input, Wih_f, Wih_b, bih_f, bih_b);
    gru_persist<<<NBLK, 512, SMEM_P>>>(Wih_f, Wih_b, Whh_f, Whh_b,
                                       bih_f, bih_b, bhh_f, bhh_b, out);
}

// round 4
// speedup vs baseline: 1.0857x; 1.0710x over previous
#include <cuda_runtime.h>
#include <math.h>

#define S 512
#define B 64
#define H 512
#define D 512
#define G3 1536   // 3*H
#define NBLK 128

// ---------------- scratch (device globals; allocation-free rule) ----------------
__device__ float g_gi0[(size_t)2 * S * B * G3];   // [dir][t][b][3H]
__device__ float g_h0[2][2][B * H];               // [parity][dir][b*H+n]
__device__ float g_h1[2][2][B * H];
__device__ unsigned g_arrive;
__device__ unsigned g_release;

// ---------------- packed f32x2 helpers ----------------
typedef unsigned long long ull;

__device__ __forceinline__ ull pk2(float x, float y) {
    ull r; asm("mov.b64 %0, {%1, %2};" : "=l"(r) : "f"(x), "f"(y)); return r;
}
__device__ __forceinline__ float2 u2f2(ull v) {
    float2 f; asm("mov.b64 {%0, %1}, %2;" : "=f"(f.x), "=f"(f.y) : "l"(v)); return f;
}
__device__ __forceinline__ void ffma2(ull& d, ull a, ull b) {
    asm("fma.rn.f32x2 %0, %1, %2, %0;" : "+l"(d) : "l"(a), "l"(b));
}
__device__ __forceinline__ float sigm(float x) { return 1.0f / (1.0f + expf(-x)); }

// ---------------- init: hidden states + barrier reset ----------------
__global__ void init_h(const float* __restrict__ enc) {
    if (blockIdx.x == 0 && threadIdx.x == 0) { g_arrive = 0; g_release = 0; }
    int idx = blockIdx.x * blockDim.x + threadIdx.x;   // 131072 total
    int layer = idx >> 16;
    int rem = idx & 65535;
    int dir = rem >> 15;
    int rem2 = rem & 32767;
    int b = rem2 >> 9;
    int n = rem2 & 511;
    float v = enc[(layer * B + b) * (2 * H) + dir * H + n];
    if (layer == 0) g_h0[0][dir][b * H + n] = v;
    else            g_h1[0][dir][b * H + n] = v;
}

// ---------------- precompute gi0 = input @ Wih0^T + bih0 (both dirs) ----------------
__global__ void gemm_gi0(const float* __restrict__ x,
                         const float* __restrict__ Wf, const float* __restrict__ Wb,
                         const float* __restrict__ bf, const float* __restrict__ bb) {
    __shared__ float As[16 * 68];
    __shared__ float Bs[16 * 68];
    int s  = blockIdx.x;
    int nb = blockIdx.y;
    int d  = blockIdx.z;
    const float* W    = d ? Wb : Wf;
    const float* bias = d ? bb : bf;

    int t = threadIdx.x;
    int lr = t >> 2;
    int lk = t & 3;
    int tx = t & 15;
    int ty = t >> 4;

    ull acc[4][2];
#pragma unroll
    for (int i = 0; i < 4; i++) { acc[i][0] = 0ull; acc[i][1] = 0ull; }

    for (int kc = 0; kc < 32; kc++) {
        __syncthreads();
        int k0 = kc * 16 + lk * 4;
        float4 av = *(const float4*)&x[((size_t)lr * S + s) * D + k0];
        As[(lk * 4 + 0) * 68 + lr] = av.x;
        As[(lk * 4 + 1) * 68 + lr] = av.y;
        As[(lk * 4 + 2) * 68 + lr] = av.z;
        As[(lk * 4 + 3) * 68 + lr] = av.w;
        float4 bv = *(const float4*)&W[(size_t)(nb * 64 + lr) * D + k0];
        Bs[(lk * 4 + 0) * 68 + lr] = bv.x;
        Bs[(lk * 4 + 1) * 68 + lr] = bv.y;
        Bs[(lk * 4 + 2) * 68 + lr] = bv.z;
        Bs[(lk * 4 + 3) * 68 + lr] = bv.w;
        __syncthreads();
#pragma unroll
        for (int kk = 0; kk < 16; kk++) {
            float4 a = *(const float4*)&As[kk * 68 + ty * 4];
            const ull* bp = (const ull*)&Bs[kk * 68 + tx * 4];
            ull b0 = bp[0], b1 = bp[1];
            ull aa;
            aa = pk2(a.x, a.x); ffma2(acc[0][0], aa, b0); ffma2(acc[0][1], aa, b1);
            aa = pk2(a.y, a.y); ffma2(acc[1][0], aa, b0); ffma2(acc[1][1], aa, b1);
            aa = pk2(a.z, a.z); ffma2(acc[2][0], aa, b0); ffma2(acc[2][1], aa, b1);
            aa = pk2(a.w, a.w); ffma2(acc[3][0], aa, b0); ffma2(acc[3][1], aa, b1);
        }
    }
    int col = nb * 64 + tx * 4;
    float4 bi4 = *(const float4*)&bias[col];
#pragma unroll
    for (int i = 0; i < 4; i++) {
        int b = ty * 4 + i;
        float2 o01 = u2f2(acc[i][0]);
        float2 o23 = u2f2(acc[i][1]);
        float4 o = make_float4(o01.x + bi4.x, o01.y + bi4.y, o23.x + bi4.z, o23.y + bi4.w);
        *(float4*)&g_gi0[(((size_t)d * S + s) * B + b) * G3 + col] = o;
    }
}

// ---------------- grid barrier (monotonic, reset by init_h each launch) ----------------
__device__ __forceinline__ void grid_bar(unsigned target) {
    __syncthreads();
    if (threadIdx.x == 0) {
        __threadfence();
        unsigned v = atomicAdd(&g_arrive, 1u) + 1u;
        if (v == target * NBLK) {
            asm volatile("st.release.gpu.u32 [%0], %1;" :: "l"(&g_release), "r"(target) : "memory");
        } else {
            unsigned r;
            do {
                asm volatile("ld.acquire.gpu.u32 %0, [%1];" : "=r"(r) : "l"(&g_release) : "memory");
            } while (r < target);
        }
    }
    __syncthreads();
}

// ---------------- cp.async helpers ----------------
__device__ __forceinline__ void cp_async16(float* smem_dst, const float* gsrc) {
    unsigned saddr = (unsigned)__cvta_generic_to_shared(smem_dst);
    asm volatile("cp.async.cg.shared.global [%0], [%1], 16;" :: "r"(saddr), "l"(gsrc));
}

// ---------------- persistent recurrence kernel ----------------
// grid 128 (= 2 dir x 64 hidden-groups of 8), block 256, 1 block/SM.
// Phase p: L0 at t=p (p<S) and L1 at t=p-1 (p>=1), one grid barrier per phase.
// Thread (mg,g,ks): 4 batch rows (mg*4..+3), 6 gate-cols (g*6..+5), k = ks (mod 4).
// 36 f32x2 accumulators per thread; 4-way K-partials reduced in smem rounds.
__global__ void __launch_bounds__(256, 1)
gru_persist(const float* __restrict__ Wih_f, const float* __restrict__ Wih_b,
            const float* __restrict__ Whh_f, const float* __restrict__ Whh_b,
            const float* __restrict__ bih_f, const float* __restrict__ bih_b,
            const float* __restrict__ bhh_f, const float* __restrict__ bhh_b,
            float* __restrict__ out) {
    extern __shared__ float sm[];
    float* WS0 = sm;                 // Whh layer0: [k 0..511][n 0..23] stride 26
    float* WSI = sm + 13312;         // Wih layer1
    float* WSH = sm + 26624;         // Whh layer1
    float* XS  = sm + 39936;         // [k 0..63][m 0..63] stride 68
    float* HS  = sm + 44288;
    float* GA  = sm + 48640;         // L0 gh  [m][n] stride 26
    float* GB  = sm + 50304;         // L1 gi
    float* GC  = sm + 51968;         // L1 gh
    float* GI0S= sm + 53632;         // gi0 prefetch [m][28]

    const int tid = threadIdx.x;
    const int bid = blockIdx.x;
    const int dir = bid >> 6;
    const int hb  = (bid & 63) * 8;

    const float* Wih  = dir ? Wih_b : Wih_f;
    const float* Whh  = dir ? Whh_b : Whh_f;
    const float* bih  = dir ? bih_b : bih_f;
    const float* bhh  = dir ? bhh_b : bhh_f;
    const float* bhh0 = bhh;
    const float* bi1  = bih + G3;
    const float* bh1  = bhh + G3;

    // ---- stage all weights once (resident for all 512 steps) ----
#pragma unroll
    for (int it = 0; it < 12; it++) {
        int fi = tid + 256 * it;           // < 3072
        int n  = fi >> 7;                  // 0..23
        int kq = fi & 127;
        int grow = (n >> 3) * H + hb + (n & 7);
        float4 v0 = *(const float4*)&Whh[(size_t)grow * H + kq * 4];
        WS0[(kq * 4 + 0) * 26 + n] = v0.x;
        WS0[(kq * 4 + 1) * 26 + n] = v0.y;
        WS0[(kq * 4 + 2) * 26 + n] = v0.z;
        WS0[(kq * 4 + 3) * 26 + n] = v0.w;
        float4 vi = *(const float4*)&Wih[(size_t)G3 * D + (size_t)grow * D + kq * 4];
        WSI[(kq * 4 + 0) * 26 + n] = vi.x;
        WSI[(kq * 4 + 1) * 26 + n] = vi.y;
        WSI[(kq * 4 + 2) * 26 + n] = vi.z;
        WSI[(kq * 4 + 3) * 26 + n] = vi.w;
        float4 vh = *(const float4*)&Whh[(size_t)G3 * H + (size_t)grow * H + kq * 4];
        WSH[(kq * 4 + 0) * 26 + n] = vh.x;
        WSH[(kq * 4 + 1) * 26 + n] = vh.y;
        WSH[(kq * 4 + 2) * 26 + n] = vh.z;
        WSH[(kq * 4 + 3) * 26 + n] = vh.w;
    }

    const int mg4 = (tid & 15) * 4;       // 4 batch rows
    const int ns  = ((tid >> 4) & 3) * 6; // 6 gate-cols
    const int ks  = tid >> 6;             // K-split (uniform per warp)

    for (int p = 0; p <= S; p++) {
        const float* X  = g_h0[p & 1][dir];          // input to L0(p) AND x-input to L1(p-1)
        const float* Hc = g_h1[(p + 1) & 1][dir];    // h1 state consumed by L1(p-1)

        // ---- prefetch gi0 tile for this phase (used in L0 epilogue) ----
        if (p < S) {
            int tt0 = dir ? (S - 1 - p) : p;
            const float* gi = &g_gi0[((size_t)dir * S + tt0) * B * G3];
            {
                int mm = tid / 6, r = tid % 6;
                if (tid < 384) {
                    int gate = r >> 1, half = r & 1;
                    cp_async16(&GI0S[mm * 28 + gate * 8 + half * 4],
                               gi + mm * G3 + gate * H + hb + half * 4);
                }
            }
            {
                int idx = tid + 256;
                if (idx < 384) {
                    int mm = idx / 6, r = idx % 6;
                    int gate = r >> 1, half = r & 1;
                    cp_async16(&GI0S[mm * 28 + gate * 8 + half * 4],
                               gi + mm * G3 + gate * H + hb + half * 4);
                }
            }
            asm volatile("cp.async.commit_group;");
        }

        ull accA[4][3], accB[4][3], accC[4][3];
#pragma unroll
        for (int mi = 0; mi < 4; mi++)
#pragma unroll
            for (int c = 0; c < 3; c++) { accA[mi][c] = 0; accB[mi][c] = 0; accC[mi][c] = 0; }

        for (int kc = 0; kc < 8; kc++) {
            __syncthreads();
#pragma unroll
            for (int it = 0; it < 4; it++) {
                int fi = tid + 256 * it;       // < 1024
                int mm = fi >> 4;
                int kq = fi & 15;
                float4 vx = __ldcg((const float4*)&X[mm * H + kc * 64 + kq * 4]);
                XS[(kq * 4 + 0) * 68 + mm] = vx.x;
                XS[(kq * 4 + 1) * 68 + mm] = vx.y;
                XS[(kq * 4 + 2) * 68 + mm] = vx.z;
                XS[(kq * 4 + 3) * 68 + mm] = vx.w;
                float4 vh = __ldcg((const float4*)&Hc[mm * H + kc * 64 + kq * 4]);
                HS[(kq * 4 + 0) * 68 + mm] = vh.x;
                HS[(kq * 4 + 1) * 68 + mm] = vh.y;
                HS[(kq * 4 + 2) * 68 + mm] = vh.z;
                HS[(kq * 4 + 3) * 68 + mm] = vh.w;
            }
            __syncthreads();
            const int kc6 = kc * 64;
#pragma unroll 2
            for (int j = 0; j < 16; j++) {
                const int kk = (j << 2) | ks;
                const float4 xv = *(const float4*)&XS[kk * 68 + mg4];
                const float4 hv = *(const float4*)&HS[kk * 68 + mg4];
                const ull* w0p = (const ull*)&WS0[(kc6 + kk) * 26 + ns];
                const ull* wip = (const ull*)&WSI[(kc6 + kk) * 26 + ns];
                const ull* whp = (const ull*)&WSH[(kc6 + kk) * 26 + ns];
                const ull w0 = w0p[0], w1 = w0p[1], w2 = w0p[2];
                const ull i0 = wip[0], i1 = wip[1], i2 = wip[2];
                const ull h0 = whp[0], h1 = whp[1], h2 = whp[2];
                ull xx, hh;
                xx = pk2(xv.x, xv.x); hh = pk2(hv.x, hv.x);
                ffma2(accA[0][0], xx, w0); ffma2(accA[0][1], xx, w1); ffma2(accA[0][2], xx, w2);
                ffma2(accB[0][0], xx, i0); ffma2(accB[0][1], xx, i1); ffma2(accB[0][2], xx, i2);
                ffma2(accC[0][0], hh, h0); ffma2(accC[0][1], hh, h1); ffma2(accC[0][2], hh, h2);
                xx = pk2(xv.y, xv.y); hh = pk2(hv.y, hv.y);
                ffma2(accA[1][0], xx, w0); ffma2(accA[1][1], xx, w1); ffma2(accA[1][2], xx, w2);
                ffma2(accB[1][0], xx, i0); ffma2(accB[1][1], xx, i1); ffma2(accB[1][2], xx, i2);
                ffma2(accC[1][0], hh, h0); ffma2(accC[1][1], hh, h1); ffma2(accC[1][2], hh, h2);
                xx = pk2(xv.z, xv.z); hh = pk2(hv.z, hv.z);
                ffma2(accA[2][0], xx, w0); ffma2(accA[2][1], xx, w1); ffma2(accA[2][2], xx, w2);
                ffma2(accB[2][0], xx, i0); ffma2(accB[2][1], xx, i1); ffma2(accB[2][2], xx, i2);
                ffma2(accC[2][0], hh, h0); ffma2(accC[2][1], hh, h1); ffma2(accC[2][2], hh, h2);
                xx = pk2(xv.w, xv.w); hh = pk2(hv.w, hv.w);
                ffma2(accA[3][0], xx, w0); ffma2(accA[3][1], xx, w1); ffma2(accA[3][2], xx, w2);
                ffma2(accB[3][0], xx, i0); ffma2(accB[3][1], xx, i1); ffma2(accB[3][2], xx, i2);
                ffma2(accC[3][0], hh, h0); ffma2(accC[3][1], hh, h1); ffma2(accC[3][2], hh, h2);
            }
        }

        // ---- K-split reduction into GA/GB/GC (4 sequential rounds) ----
#pragma unroll
        for (int r = 0; r < 4; r++) {
            if (ks == r) {
#pragma unroll
                for (int mi = 0; mi < 4; mi++) {
                    int mrow = (mg4 + mi) * 26 + ns;
                    float2* ga = (float2*)&GA[mrow];
                    float2* gb = (float2*)&GB[mrow];
                    float2* gc = (float2*)&GC[mrow];
#pragma unroll
                    for (int c = 0; c < 3; c++) {
                        float2 va = u2f2(accA[mi][c]);
                        float2 vb = u2f2(accB[mi][c]);
                        float2 vc = u2f2(accC[mi][c]);
                        if (r) {
                            float2 o;
                            o = ga[c]; va.x += o.x; va.y += o.y;
                            o = gb[c]; vb.x += o.x; vb.y += o.y;
                            o = gc[c]; vc.x += o.x; vc.y += o.y;
                        }
                        ga[c] = va; gb[c] = vb; gc[c] = vc;
                    }
                }
            }
            __syncthreads();
        }
        asm volatile("cp.async.wait_group 0;");
        __syncthreads();

        // ---- L0 epilogue: t = p ----
        if (p < S) {
            float* Xn = g_h0[(p + 1) & 1][dir];
#pragma unroll
            for (int it = 0; it < 2; it++) {
                int idx = tid + 256 * it;         // < 512
                int mm = idx & 63;
                int j  = idx >> 6;
                int row = hb + j;
                float hr = GA[mm * 26 + j]      + bhh0[row];
                float hz = GA[mm * 26 + 8 + j]  + bhh0[H + row];
                float hn = GA[mm * 26 + 16 + j] + bhh0[2 * H + row];
                float r  = sigm(GI0S[mm * 28 + j] + hr);
                float z  = sigm(GI0S[mm * 28 + 8 + j] + hz);
                float nn = tanhf(GI0S[mm * 28 + 16 + j] + r * hn);
                float hp = __ldcg(&X[mm * H + row]);
                Xn[mm * H + row] = (1.0f - z) * nn + z * hp;
            }
        }

        // ---- L1 epilogue: t = p-1 ----
        if (p >= 1) {
            int t1 = p - 1;
            int tt = dir ? (S - 1 - t1) : t1;
            float* Hn = g_h1[p & 1][dir];
#pragma unroll
            for (int it = 0; it < 2; it++) {
                int idx = tid + 256 * it;
                int mm = idx & 63;
                int j  = idx >> 6;
                int row = hb + j;
                float ir  = GB[mm * 26 + j]      + bi1[row];
                float iz  = GB[mm * 26 + 8 + j]  + bi1[H + row];
                float inn = GB[mm * 26 + 16 + j] + bi1[2 * H + row];
                float hr  = GC[mm * 26 + j]      + bh1[row];
                float hz  = GC[mm * 26 + 8 + j]  + bh1[H + row];
                float hn  = GC[mm * 26 + 16 + j] + bh1[2 * H + row];
                float r  = sigm(ir + hr);
                float z  = sigm(iz + hz);
                float nn = tanhf(inn + r * hn);
                float hp = __ldcg(&Hc[mm * H + row]);
                float hnew = (1.0f - z) * nn + z * hp;
                Hn[mm * H + row] = hnew;
                out[(size_t)mm * (S * 2 * H) + (size_t)tt * (2 * H) + dir * H + row] = hnew;
            }
        }

        grid_bar((unsigned)(p + 1));
    }

    // ---- final hidden state copy (h0/h1 parity S&1 == 0) ----
#pragma unroll
    for (int it = 0; it < 4; it++) {
        int idx = bid * 1024 + it * 256 + tid;    // < 131072
        int l = idx >> 16;
        int b = (idx >> 10) & 63;
        int d = (idx >> 9) & 1;
        int n = idx & 511;
        float v = l ? __ldcg(&g_h1[0][d][b * H + n]) : __ldcg(&g_h0[0][d][b * H + n]);
        out[(size_t)B * S * 2 * H + idx] = v;
    }
}

// ---------------- launch ----------------
extern "C" void kernel_launch(void* const* d_in, const int* in_sizes, int n_in,
                              void* d_out, int out_size) {
    const float* input  = (const float*)d_in[0];
    const float* enc    = (const float*)d_in[1];
    const float* Wih_f  = (const float*)d_in[2];
    const float* Whh_f  = (const float*)d_in[3];
    const float* bih_f  = (const float*)d_in[4];
    const float* bhh_f  = (const float*)d_in[5];
    const float* Wih_b  = (const float*)d_in[6];
    const float* Whh_b  = (const float*)d_in[7];
    const float* bih_b  = (const float*)d_in[8];
    const float* bhh_b  = (const float*)d_in[9];
    float* out = (float*)d_out;

    const int SMEM_P = 55424 * 4;   // 221696 B
    static int configured = 0;
    if (!configured) {
        cudaFuncSetAttribute(gru_persist, cudaFuncAttributeMaxDynamicSharedMemorySize, SMEM_P);
        configured = 1;
    }

    init_h<<<512, 256>>>(enc);
    gemm_gi0<<<dim3(S, 24, 2), 256>>>(input, Wih_f, Wih_b, bih_f, bih_b);
    gru_persist<<<NBLK, 256, SMEM_P>>>(Wih_f, Wih_b, Whh_f, Whh_b,
                                       bih_f, bih_b, bhh_f, bhh_b, out);
}

// round 5
// speedup vs baseline: 2.1270x; 1.9591x over previous
#include <cuda_runtime.h>
#include <cuda_bf16.h>
#include <math.h>

#define S 512
#define B 64
#define H 512
#define D 512
#define G3 1536
#define NBLK 128

typedef unsigned u32;
typedef __nv_bfloat16 bf16;

// ---------------- device-global scratch (allocation-free rule) ----------------
__device__ float g_gi0[(size_t)2 * S * B * G3];          // fp32 gi0 [dir][t][b][3H]
__device__ bf16  g_xp[2][(size_t)B * S * D];             // input hi/lo planes
__device__ bf16  g_wp[2][2][(size_t)G3 * D];             // Wih layer0 [dir][plane]
__device__ float g_h0f[2][2][B * H];                     // [parity][dir]
__device__ float g_h1f[2][2][B * H];
__device__ bf16  g_h0p[2][2][2][B * H];                  // [parity][dir][plane]
__device__ bf16  g_h1p[2][2][2][B * H];
__device__ unsigned g_arrive;
__device__ unsigned g_release;

// ---------------- helpers ----------------
__device__ __forceinline__ u32 pbf2(float x, float y) {
    u32 a = (u32)__bfloat16_as_ushort(__float2bfloat16(x));
    u32 b = (u32)__bfloat16_as_ushort(__float2bfloat16(y));
    return a | (b << 16);
}
__device__ __forceinline__ void split_bf(float v, bf16& hi, bf16& lo) {
    hi = __float2bfloat16(v);
    lo = __float2bfloat16(v - __bfloat162float(hi));
}
__device__ __forceinline__ float sigm(float x) { return 1.0f / (1.0f + expf(-x)); }

__device__ __forceinline__ void mma16816(float* d, const u32* a, u32 b0, u32 b1) {
    asm volatile("mma.sync.aligned.m16n8k16.row.col.f32.bf16.bf16.f32 "
                 "{%0,%1,%2,%3},{%4,%5,%6,%7},{%8,%9},{%0,%1,%2,%3};"
                 : "+f"(d[0]), "+f"(d[1]), "+f"(d[2]), "+f"(d[3])
                 : "r"(a[0]), "r"(a[1]), "r"(a[2]), "r"(a[3]), "r"(b0), "r"(b1));
}
__device__ __forceinline__ void ldm4(u32* r, const void* p) {
    u32 s = (u32)__cvta_generic_to_shared(p);
    asm volatile("ldmatrix.sync.aligned.m8n8.x4.shared.b16 {%0,%1,%2,%3},[%4];"
                 : "=r"(r[0]), "=r"(r[1]), "=r"(r[2]), "=r"(r[3]) : "r"(s));
}
__device__ __forceinline__ void cp16(void* smem_dst, const void* gsrc) {
    u32 s = (u32)__cvta_generic_to_shared(smem_dst);
    asm volatile("cp.async.cg.shared.global [%0], [%1], 16;" :: "r"(s), "l"(gsrc));
}

// ---------------- init: hidden states (fp32 + planes) + barrier reset ----------------
__global__ void init_h(const float* __restrict__ enc) {
    if (blockIdx.x == 0 && threadIdx.x == 0) { g_arrive = 0; g_release = 0; }
    int idx = blockIdx.x * blockDim.x + threadIdx.x;   // 131072
    int layer = idx >> 16;
    int rem = idx & 65535;
    int dir = rem >> 15;
    int rem2 = rem & 32767;
    int b = rem2 >> 9;
    int n = rem2 & 511;
    float v = enc[(layer * B + b) * (2 * H) + dir * H + n];
    bf16 hi, lo; split_bf(v, hi, lo);
    if (layer == 0) {
        g_h0f[0][dir][b * H + n] = v;
        g_h0p[0][dir][0][b * H + n] = hi;
        g_h0p[0][dir][1][b * H + n] = lo;
    } else {
        g_h1f[0][dir][b * H + n] = v;
        g_h1p[0][dir][0][b * H + n] = hi;
        g_h1p[0][dir][1][b * H + n] = lo;
    }
}

// ---------------- conversion kernels ----------------
__global__ void conv_x(const float* __restrict__ x) {
    size_t i = ((size_t)blockIdx.x * 256 + threadIdx.x) * 4;   // 16384 blocks
    float4 v = *(const float4*)&x[i];
    bf16 h0, l0, h1, l1, h2, l2, h3, l3;
    split_bf(v.x, h0, l0); split_bf(v.y, h1, l1);
    split_bf(v.z, h2, l2); split_bf(v.w, h3, l3);
    u32* ph = (u32*)&g_xp[0][i];
    u32* pl = (u32*)&g_xp[1][i];
    ph[0] = (u32)__bfloat16_as_ushort(h0) | ((u32)__bfloat16_as_ushort(h1) << 16);
    ph[1] = (u32)__bfloat16_as_ushort(h2) | ((u32)__bfloat16_as_ushort(h3) << 16);
    pl[0] = (u32)__bfloat16_as_ushort(l0) | ((u32)__bfloat16_as_ushort(l1) << 16);
    pl[1] = (u32)__bfloat16_as_ushort(l2) | ((u32)__bfloat16_as_ushort(l3) << 16);
}
__global__ void conv_w(const float* __restrict__ wf, const float* __restrict__ wb) {
    size_t i = ((size_t)blockIdx.x * 256 + threadIdx.x) * 4;   // 1536 blocks -> 2*786432
    int d = i >= (size_t)G3 * D;
    size_t off = d ? i - (size_t)G3 * D : i;
    const float* src = d ? wb : wf;                 // layer0 = first G3*D elems
    float4 v = *(const float4*)&src[off];
    bf16 h0, l0, h1, l1, h2, l2, h3, l3;
    split_bf(v.x, h0, l0); split_bf(v.y, h1, l1);
    split_bf(v.z, h2, l2); split_bf(v.w, h3, l3);
    u32* ph = (u32*)&g_wp[d][0][off];
    u32* pl = (u32*)&g_wp[d][1][off];
    ph[0] = (u32)__bfloat16_as_ushort(h0) | ((u32)__bfloat16_as_ushort(h1) << 16);
    ph[1] = (u32)__bfloat16_as_ushort(h2) | ((u32)__bfloat16_as_ushort(h3) << 16);
    pl[0] = (u32)__bfloat16_as_ushort(l0) | ((u32)__bfloat16_as_ushort(l1) << 16);
    pl[1] = (u32)__bfloat16_as_ushort(l2) | ((u32)__bfloat16_as_ushort(l3) << 16);
}

// ---------------- gi0 = input @ Wih0^T + bih0, split-bf16 mma ----------------
// grid (S, 12, 2), 256 thr = 8 warps (4 mtiles x 2 nhalves). Tile M=64, N=128, K=512.
__global__ void __launch_bounds__(256, 1)
gemm_gi0(const float* __restrict__ bf_, const float* __restrict__ bb_) {
    extern __shared__ char sm2[];
    char* Wbuf0 = sm2;                 // [plane][128][36 u32] = 36864 per buf
    char* Wbuf1 = sm2 + 36864;
    char* Xbuf0 = sm2 + 73728;         // [plane][64][72 bf16] = 18432 per buf
    char* Xbuf1 = sm2 + 92160;

    int s  = blockIdx.x;
    int nb = blockIdx.y;
    int d  = blockIdx.z;
    const float* bias = d ? bb_ : bf_;

    int tid = threadIdx.x;
    int w = tid >> 5, l = tid & 31;
    int mtile = w & 3, m0 = mtile * 16, nh = w >> 2;

    const char* wsrc[2] = { (const char*)&g_wp[d][0][(size_t)(nb * 128) * D],
                            (const char*)&g_wp[d][1][(size_t)(nb * 128) * D] };
    const char* xsrc[2] = { (const char*)&g_xp[0][0], (const char*)&g_xp[1][0] };

    float acc[8][4];
#pragma unroll
    for (int nt = 0; nt < 8; nt++) { acc[nt][0] = acc[nt][1] = acc[nt][2] = acc[nt][3] = 0.f; }

    // stage chunk c into buffers
    auto stage = [&](int c, char* Wb, char* Xb) {
#pragma unroll
        for (int i = 0; i < 8; i++) {
            int idx = i * 256 + tid;              // < 2048
            int pl = idx >> 10, row = (idx >> 3) & 127, seg = idx & 7;
            cp16(Wb + pl * 18432 + row * 144 + seg * 16,
                 wsrc[pl] + (size_t)row * 1024 + c * 128 + seg * 16);
        }
#pragma unroll
        for (int i = 0; i < 4; i++) {
            int idx = i * 256 + tid;              // < 1024
            int pl = idx >> 9, row = (idx >> 3) & 63, seg = idx & 7;
            cp16(Xb + pl * 9216 + row * 144 + seg * 16,
                 xsrc[pl] + (size_t)row * 524288 + (size_t)s * 1024 + c * 128 + seg * 16);
        }
        asm volatile("cp.async.commit_group;");
    };

    stage(0, Wbuf0, Xbuf0);

    for (int c = 0; c < 8; c++) {
        asm volatile("cp.async.wait_group 0;");
        __syncthreads();
        if (c < 7) stage(c + 1, (c & 1) ? Wbuf0 : Wbuf1, (c & 1) ? Xbuf0 : Xbuf1);
        char* Wb = (c & 1) ? Wbuf1 : Wbuf0;
        char* Xb = (c & 1) ? Xbuf1 : Xbuf0;
#pragma unroll
        for (int kl = 0; kl < 4; kl++) {
            u32 ah[4], al[4];
            int aoff = (m0 + (l & 15)) * 144 + kl * 32 + (l >> 4) * 16;
            ldm4(ah, Xb + aoff);
            ldm4(al, Xb + 9216 + aoff);
            const u32* Wh = (const u32*)Wb;
            const u32* Wl = (const u32*)(Wb + 18432);
#pragma unroll
            for (int nt = 0; nt < 8; nt++) {
                int nrow = nh * 64 + nt * 8 + (l >> 2);
                int wi = nrow * 36 + kl * 8 + (l & 3);
                u32 bh0 = Wh[wi], bh1 = Wh[wi + 4];
                u32 bl0 = Wl[wi], bl1 = Wl[wi + 4];
                mma16816(acc[nt], ah, bh0, bh1);
                mma16816(acc[nt], al, bh0, bh1);
                mma16816(acc[nt], ah, bl0, bl1);
            }
        }
    }

    // epilogue: bias + store fp32
#pragma unroll
    for (int nt = 0; nt < 8; nt++) {
        int col = nb * 128 + nh * 64 + nt * 8 + 2 * (l & 3);
        float2 bi = *(const float2*)&bias[col];
        int b0 = m0 + (l >> 2);
        float2 v0 = make_float2(acc[nt][0] + bi.x, acc[nt][1] + bi.y);
        float2 v1 = make_float2(acc[nt][2] + bi.x, acc[nt][3] + bi.y);
        *(float2*)&g_gi0[(((size_t)d * S + s) * B + b0) * G3 + col] = v0;
        *(float2*)&g_gi0[(((size_t)d * S + s) * B + b0 + 8) * G3 + col] = v1;
    }
}

// ---------------- grid barrier ----------------
__device__ __forceinline__ void grid_bar(unsigned target) {
    __syncthreads();
    if (threadIdx.x == 0) {
        __threadfence();
        unsigned v = atomicAdd(&g_arrive, 1u) + 1u;
        if (v == target * NBLK) {
            asm volatile("st.release.gpu.u32 [%0], %1;" :: "l"(&g_release), "r"(target) : "memory");
        } else {
            unsigned r;
            do {
                asm volatile("ld.acquire.gpu.u32 %0, [%1];" : "=r"(r) : "l"(&g_release) : "memory");
            } while (r < target);
        }
    }
    __syncthreads();
}

// ---------------- persistent recurrence kernel (split-bf16 mma) ----------------
// grid 128 (2 dir x 64 hgroups of 8), 512 thr = 16 warps (mtile x4, ksub x4).
// smem: WS 149760 | buf0 36864 (GA/GB/GC alias) | buf1 36864 | GI0S 7168 = 230656 B
__global__ void __launch_bounds__(512, 1)
gru_persist(const float* __restrict__ Wih_f, const float* __restrict__ Wih_b,
            const float* __restrict__ Whh_f, const float* __restrict__ Whh_b,
            const float* __restrict__ bih_f, const float* __restrict__ bih_b,
            const float* __restrict__ bhh_f, const float* __restrict__ bhh_b,
            float* __restrict__ out) {
    extern __shared__ char smem[];
    u32*  WS   = (u32*)smem;                     // [(mat*2+plane)*24 + n][260 u32]
    char* buf0 = smem + 149760;                  // 4 planes x [64][72] bf16
    char* buf1 = smem + 186624;
    float* GI0S = (float*)(smem + 223488);       // [64][28]
    float* GA = (float*)buf0;                    // [64][26] aliased after mma loop
    float* GB = (float*)(buf0 + 6656);
    float* GC = (float*)(buf0 + 13312);

    const int tid = threadIdx.x;
    const int bid = blockIdx.x;
    const int dir = bid >> 6;
    const int hb  = (bid & 63) * 8;
    const int w = tid >> 5, l = tid & 31;
    const int mtile = w & 3, m0 = mtile * 16, ksub = w >> 2;

    const float* Wih = dir ? Wih_b : Wih_f;
    const float* Whh = dir ? Whh_b : Whh_f;
    const float* bih = dir ? bih_b : bih_f;
    const float* bhh = dir ? bhh_b : bhh_f;
    const float* bhh0 = bhh;
    const float* bi1 = bih + G3;
    const float* bh1 = bhh + G3;

    // ---- one-time weight staging: convert to bf16 hi/lo u32-pairs ----
    {
        const float* Wmat[3] = { Whh, Wih + (size_t)G3 * D, Whh + (size_t)G3 * H };
#pragma unroll 4
        for (int i = 0; i < 36; i++) {
            int item = tid + 512 * i;            // < 18432 = 3*24*256
            int m3 = item / 6144;
            int rem = item - m3 * 6144;
            int n = rem >> 8;
            int k2 = rem & 255;
            int grow = (n >> 3) * H + hb + (n & 7);
            float2 v = *(const float2*)(Wmat[m3] + (size_t)grow * 512 + 2 * k2);
            bf16 h0, l0, h1, l1;
            split_bf(v.x, h0, l0); split_bf(v.y, h1, l1);
            WS[((m3 * 2 + 0) * 24 + n) * 260 + k2] =
                (u32)__bfloat16_as_ushort(h0) | ((u32)__bfloat16_as_ushort(h1) << 16);
            WS[((m3 * 2 + 1) * 24 + n) * 260 + k2] =
                (u32)__bfloat16_as_ushort(l0) | ((u32)__bfloat16_as_ushort(l1) << 16);
        }
    }

    for (int p = 0; p <= S; p++) {
        const char* Xh = (const char*)g_h0p[p & 1][dir][0];
        const char* Xl = (const char*)g_h0p[p & 1][dir][1];
        const char* Hh = (const char*)g_h1p[(p + 1) & 1][dir][0];
        const char* Hl = (const char*)g_h1p[(p + 1) & 1][dir][1];
        const float* Xf = g_h0f[p & 1][dir];
        const float* Hf = g_h1f[(p + 1) & 1][dir];

        // stage chunk c of h planes
        const char* psrc[4] = { Xh, Xl, Hh, Hl };
        auto stage = [&](int c, char* bb) {
            int row = tid >> 3, seg = tid & 7;   // 512 thr -> row<64
#pragma unroll
            for (int pl = 0; pl < 4; pl++) {
                cp16(bb + pl * 9216 + row * 144 + seg * 16,
                     psrc[pl] + row * 1024 + c * 128 + seg * 16);
            }
        };

        // prefetch gi0 tile + chunk 0, single commit group
        if (p < S) {
            int tt0 = dir ? (S - 1 - p) : p;
            const float* gi = &g_gi0[((size_t)dir * S + tt0) * B * G3];
            if (tid < 384) {
                int mm = tid / 6, r = tid % 6;
                int gate = r >> 1, half = r & 1;
                cp16(&GI0S[mm * 28 + gate * 8 + half * 4],
                     gi + mm * G3 + gate * H + hb + half * 4);
            }
        }
        stage(0, buf0);
        asm volatile("cp.async.commit_group;");

        float acc[3][3][4];
#pragma unroll
        for (int m3 = 0; m3 < 3; m3++)
#pragma unroll
            for (int nt = 0; nt < 3; nt++)
                acc[m3][nt][0] = acc[m3][nt][1] = acc[m3][nt][2] = acc[m3][nt][3] = 0.f;

        for (int c = 0; c < 8; c++) {
            asm volatile("cp.async.wait_group 0;");
            __syncthreads();
            if (c < 7) {
                stage(c + 1, (c & 1) ? buf0 : buf1);
                asm volatile("cp.async.commit_group;");
            }
            char* bb = (c & 1) ? buf1 : buf0;
            u32 ah[4], al[4], hh4[4], hl4[4];
            int aoff = (m0 + (l & 15)) * 144 + ksub * 32 + (l >> 4) * 16;
            ldm4(ah,  bb + aoff);
            ldm4(al,  bb + 9216  + aoff);
            ldm4(hh4, bb + 18432 + aoff);
            ldm4(hl4, bb + 27648 + aoff);
            int k2b = c * 32 + ksub * 8;
#pragma unroll
            for (int m3 = 0; m3 < 3; m3++) {
                const u32* A  = (m3 == 2) ? hh4 : ah;
                const u32* Al = (m3 == 2) ? hl4 : al;
#pragma unroll
                for (int nt = 0; nt < 3; nt++) {
                    int rbase = ((m3 * 2) * 24 + nt * 8 + (l >> 2)) * 260 + k2b + (l & 3);
                    u32 bh0 = WS[rbase], bh1 = WS[rbase + 4];
                    u32 bl0 = WS[rbase + 24 * 260], bl1 = WS[rbase + 24 * 260 + 4];
                    mma16816(acc[m3][nt], A,  bh0, bh1);
                    mma16816(acc[m3][nt], Al, bh0, bh1);
                    mma16816(acc[m3][nt], A,  bl0, bl1);
                }
            }
        }

        // ---- K-split reduction into GA/GB/GC (aliases buf0; chunk7 used buf1) ----
#pragma unroll
        for (int r = 0; r < 4; r++) {
            if (ksub == r) {
#pragma unroll
                for (int m3 = 0; m3 < 3; m3++) {
                    float* G = (m3 == 0) ? GA : (m3 == 1) ? GB : GC;
#pragma unroll
                    for (int nt = 0; nt < 3; nt++) {
                        int col = nt * 8 + 2 * (l & 3);
                        int r0 = m0 + (l >> 2);
                        float2* p0 = (float2*)&G[r0 * 26 + col];
                        float2* p1 = (float2*)&G[(r0 + 8) * 26 + col];
                        float2 v0 = make_float2(acc[m3][nt][0], acc[m3][nt][1]);
                        float2 v1 = make_float2(acc[m3][nt][2], acc[m3][nt][3]);
                        if (r) {
                            float2 o;
                            o = *p0; v0.x += o.x; v0.y += o.y;
                            o = *p1; v1.x += o.x; v1.y += o.y;
                        }
                        *p0 = v0; *p1 = v1;
                    }
                }
            }
            __syncthreads();
        }

        // ---- L0 epilogue: t = p ----
        if (p < S) {
            float* Xnf = g_h0f[(p + 1) & 1][dir];
            bf16* Xnh = g_h0p[(p + 1) & 1][dir][0];
            bf16* Xnl = g_h0p[(p + 1) & 1][dir][1];
            int mm = tid & 63;
            int j  = tid >> 6;              // 0..7
            int row = hb + j;
            float hr = GA[mm * 26 + j]      + bhh0[row];
            float hz = GA[mm * 26 + 8 + j]  + bhh0[H + row];
            float hn = GA[mm * 26 + 16 + j] + bhh0[2 * H + row];
            float rr = sigm(GI0S[mm * 28 + j] + hr);
            float zz = sigm(GI0S[mm * 28 + 8 + j] + hz);
            float nn = tanhf(GI0S[mm * 28 + 16 + j] + rr * hn);
            float hp = __ldcg(&Xf[mm * H + row]);
            float hnew = (1.0f - zz) * nn + zz * hp;
            Xnf[mm * H + row] = hnew;
            bf16 hi, lo; split_bf(hnew, hi, lo);
            Xnh[mm * H + row] = hi;
            Xnl[mm * H + row] = lo;
        }

        // ---- L1 epilogue: t = p-1 ----
        if (p >= 1) {
            int t1 = p - 1;
            int tt = dir ? (S - 1 - t1) : t1;
            float* Hnf = g_h1f[p & 1][dir];
            bf16* Hnh = g_h1p[p & 1][dir][0];
            bf16* Hnl = g_h1p[p & 1][dir][1];
            int mm = tid & 63;
            int j  = tid >> 6;
            int row = hb + j;
            float ir  = GB[mm * 26 + j]      + bi1[row];
            float iz  = GB[mm * 26 + 8 + j]  + bi1[H + row];
            float inn = GB[mm * 26 + 16 + j] + bi1[2 * H + row];
            float hr  = GC[mm * 26 + j]      + bh1[row];
            float hz  = GC[mm * 26 + 8 + j]  + bh1[H + row];
            float hn  = GC[mm * 26 + 16 + j] + bh1[2 * H + row];
            float rr = sigm(ir + hr);
            float zz = sigm(iz + hz);
            float nn = tanhf(inn + rr * hn);
            float hp = __ldcg(&Hf[mm * H + row]);
            float hnew = (1.0f - zz) * nn + zz * hp;
            Hnf[mm * H + row] = hnew;
            bf16 hi, lo; split_bf(hnew, hi, lo);
            Hnh[mm * H + row] = hi;
            Hnl[mm * H + row] = lo;
            out[(size_t)mm * (S * 2 * H) + (size_t)tt * (2 * H) + dir * H + row] = hnew;
        }

        grid_bar((unsigned)(p + 1));
    }

    // ---- final hidden state copy (parity 0) ----
#pragma unroll
    for (int it = 0; it < 2; it++) {
        int idx = bid * 1024 + it * 512 + tid;    // < 131072
        int lyr = idx >> 16;
        int b = (idx >> 10) & 63;
        int d = (idx >> 9) & 1;
        int n = idx & 511;
        float v = lyr ? __ldcg(&g_h1f[0][d][b * H + n]) : __ldcg(&g_h0f[0][d][b * H + n]);
        out[(size_t)B * S * 2 * H + idx] = v;
    }
}

// ---------------- launch ----------------
extern "C" void kernel_launch(void* const* d_in, const int* in_sizes, int n_in,
                              void* d_out, int out_size) {
    const float* input  = (const float*)d_in[0];
    const float* enc    = (const float*)d_in[1];
    const float* Wih_f  = (const float*)d_in[2];
    const float* Whh_f  = (const float*)d_in[3];
    const float* bih_f  = (const float*)d_in[4];
    const float* bhh_f  = (const float*)d_in[5];
    const float* Wih_b  = (const float*)d_in[6];
    const float* Whh_b  = (const float*)d_in[7];
    const float* bih_b  = (const float*)d_in[8];
    const float* bhh_b  = (const float*)d_in[9];
    float* out = (float*)d_out;

    const int SMEM_G = 110592;
    const int SMEM_P = 230656;
    static int configured = 0;
    if (!configured) {
        cudaFuncSetAttribute(gemm_gi0, cudaFuncAttributeMaxDynamicSharedMemorySize, SMEM_G);
        cudaFuncSetAttribute(gru_persist, cudaFuncAttributeMaxDynamicSharedMemorySize, SMEM_P);
        configured = 1;
    }

    init_h<<<512, 256>>>(enc);
    conv_x<<<16384, 256>>>(input);
    conv_w<<<1536, 256>>>(Wih_f, Wih_b);
    gemm_gi0<<<dim3(S, 12, 2), 256, SMEM_G>>>(bih_f, bih_b);
    gru_persist<<<NBLK, 512, SMEM_P>>>(Wih_f, Wih_b, Whh_f, Whh_b,
                                       bih_f, bih_b, bhh_f, bhh_b, out);
}

// round 6
// speedup vs baseline: 2.2857x; 1.0746x over previous
#include <cuda_runtime.h>
#include <cuda_bf16.h>
#include <math.h>

#define S 512
#define B 64
#define H 512
#define D 512
#define G3 1536
#define NBLK 128

typedef unsigned u32;
typedef unsigned long long ull;
typedef __nv_bfloat16 bf16;

// ---------------- device-global scratch (allocation-free rule) ----------------
__device__ float g_gi0[(size_t)2 * S * B * G3];          // fp32 gi0 [dir][t][b][3H]
__device__ bf16  g_xp[2][(size_t)B * S * D];             // input hi/lo planes
__device__ bf16  g_wp[2][2][(size_t)G3 * D];             // Wih layer0 [dir][plane]
__device__ float g_h0f[2][2][B * H];                     // [parity][dir]
__device__ float g_h1f[2][2][B * H];
__device__ bf16  g_h0p[2][2][2][B * H];                  // [parity][dir][plane]
__device__ bf16  g_h1p[2][2][2][B * H];
__device__ unsigned g_arrive2[2];
__device__ unsigned g_release2[2];

// ---------------- helpers ----------------
__device__ __forceinline__ void split_bf(float v, bf16& hi, bf16& lo) {
    hi = __float2bfloat16(v);
    lo = __float2bfloat16(v - __bfloat162float(hi));
}
__device__ __forceinline__ float sigm(float x) { return 1.0f / (1.0f + expf(-x)); }

__device__ __forceinline__ void mma16816(float* d, const u32* a, u32 b0, u32 b1) {
    asm volatile("mma.sync.aligned.m16n8k16.row.col.f32.bf16.bf16.f32 "
                 "{%0,%1,%2,%3},{%4,%5,%6,%7},{%8,%9},{%0,%1,%2,%3};"
                 : "+f"(d[0]), "+f"(d[1]), "+f"(d[2]), "+f"(d[3])
                 : "r"(a[0]), "r"(a[1]), "r"(a[2]), "r"(a[3]), "r"(b0), "r"(b1));
}
__device__ __forceinline__ void ldm4(u32* r, const void* p) {
    u32 s = (u32)__cvta_generic_to_shared(p);
    asm volatile("ldmatrix.sync.aligned.m8n8.x4.shared.b16 {%0,%1,%2,%3},[%4];"
                 : "=r"(r[0]), "=r"(r[1]), "=r"(r[2]), "=r"(r[3]) : "r"(s));
}
__device__ __forceinline__ void cp16(void* smem_dst, const void* gsrc) {
    u32 s = (u32)__cvta_generic_to_shared(smem_dst);
    asm volatile("cp.async.cg.shared.global [%0], [%1], 16;" :: "r"(s), "l"(gsrc));
}

// ---------------- pad kernel: shifts gru_persist into ncu's -s 5 slot ----------------
__global__ void pad_k() {}

// ---------------- init: hidden states (fp32 + planes) + barrier reset ----------------
__global__ void init_h(const float* __restrict__ enc) {
    if (blockIdx.x == 0 && threadIdx.x < 2) {
        g_arrive2[threadIdx.x] = 0;
        g_release2[threadIdx.x] = 0;
    }
    int idx = blockIdx.x * blockDim.x + threadIdx.x;   // 131072
    int layer = idx >> 16;
    int rem = idx & 65535;
    int dir = rem >> 15;
    int rem2 = rem & 32767;
    int b = rem2 >> 9;
    int n = rem2 & 511;
    float v = enc[(layer * B + b) * (2 * H) + dir * H + n];
    bf16 hi, lo; split_bf(v, hi, lo);
    if (layer == 0) {
        g_h0f[0][dir][b * H + n] = v;
        g_h0p[0][dir][0][b * H + n] = hi;
        g_h0p[0][dir][1][b * H + n] = lo;
    } else {
        g_h1f[0][dir][b * H + n] = v;
        g_h1p[0][dir][0][b * H + n] = hi;
        g_h1p[0][dir][1][b * H + n] = lo;
    }
}

// ---------------- conversion kernels ----------------
__global__ void conv_x(const float* __restrict__ x) {
    size_t i = ((size_t)blockIdx.x * 256 + threadIdx.x) * 4;   // 16384 blocks
    float4 v = *(const float4*)&x[i];
    bf16 h0, l0, h1, l1, h2, l2, h3, l3;
    split_bf(v.x, h0, l0); split_bf(v.y, h1, l1);
    split_bf(v.z, h2, l2); split_bf(v.w, h3, l3);
    u32* ph = (u32*)&g_xp[0][i];
    u32* pl = (u32*)&g_xp[1][i];
    ph[0] = (u32)__bfloat16_as_ushort(h0) | ((u32)__bfloat16_as_ushort(h1) << 16);
    ph[1] = (u32)__bfloat16_as_ushort(h2) | ((u32)__bfloat16_as_ushort(h3) << 16);
    pl[0] = (u32)__bfloat16_as_ushort(l0) | ((u32)__bfloat16_as_ushort(l1) << 16);
    pl[1] = (u32)__bfloat16_as_ushort(l2) | ((u32)__bfloat16_as_ushort(l3) << 16);
}
__global__ void conv_w(const float* __restrict__ wf, const float* __restrict__ wb) {
    size_t i = ((size_t)blockIdx.x * 256 + threadIdx.x) * 4;   // 1536 blocks
    int d = i >= (size_t)G3 * D;
    size_t off = d ? i - (size_t)G3 * D : i;
    const float* src = d ? wb : wf;
    float4 v = *(const float4*)&src[off];
    bf16 h0, l0, h1, l1, h2, l2, h3, l3;
    split_bf(v.x, h0, l0); split_bf(v.y, h1, l1);
    split_bf(v.z, h2, l2); split_bf(v.w, h3, l3);
    u32* ph = (u32*)&g_wp[d][0][off];
    u32* pl = (u32*)&g_wp[d][1][off];
    ph[0] = (u32)__bfloat16_as_ushort(h0) | ((u32)__bfloat16_as_ushort(h1) << 16);
    ph[1] = (u32)__bfloat16_as_ushort(h2) | ((u32)__bfloat16_as_ushort(h3) << 16);
    pl[0] = (u32)__bfloat16_as_ushort(l0) | ((u32)__bfloat16_as_ushort(l1) << 16);
    pl[1] = (u32)__bfloat16_as_ushort(l2) | ((u32)__bfloat16_as_ushort(l3) << 16);
}

// ---------------- gi0 = input @ Wih0^T + bih0, split-bf16 mma ----------------
// grid (S, 24, 2), 256 thr = 8 warps (4 mtiles x 2 nhalves of 32). M=64, N=64, K=512.
// smem 73728 -> 3 blocks/SM.
__global__ void __launch_bounds__(256, 3)
gemm_gi0(const float* __restrict__ bf_, const float* __restrict__ bb_) {
    extern __shared__ char sm2[];
    char* Wbuf0 = sm2;                 // 2 planes x [64][72 bf16] = 18432
    char* Wbuf1 = sm2 + 18432;
    char* Xbuf0 = sm2 + 36864;
    char* Xbuf1 = sm2 + 55296;

    int s  = blockIdx.x;
    int nb = blockIdx.y;
    int d  = blockIdx.z;
    const float* bias = d ? bb_ : bf_;

    int tid = threadIdx.x;
    int w = tid >> 5, l = tid & 31;
    int mtile = w & 3, m0 = mtile * 16, nh = w >> 2;

    const char* wsrc[2] = { (const char*)&g_wp[d][0][(size_t)(nb * 64) * D],
                            (const char*)&g_wp[d][1][(size_t)(nb * 64) * D] };
    const char* xsrc[2] = { (const char*)&g_xp[0][0], (const char*)&g_xp[1][0] };

    float acc[4][4];
#pragma unroll
    for (int nt = 0; nt < 4; nt++) { acc[nt][0] = acc[nt][1] = acc[nt][2] = acc[nt][3] = 0.f; }

    auto stage = [&](int c, char* Wb, char* Xb) {
#pragma unroll
        for (int i = 0; i < 4; i++) {
            int idx = i * 256 + tid;              // < 1024
            int pl = idx >> 9, row = (idx >> 3) & 63, seg = idx & 7;
            cp16(Wb + pl * 9216 + row * 144 + seg * 16,
                 wsrc[pl] + (size_t)row * 1024 + c * 128 + seg * 16);
        }
#pragma unroll
        for (int i = 0; i < 4; i++) {
            int idx = i * 256 + tid;              // < 1024
            int pl = idx >> 9, row = (idx >> 3) & 63, seg = idx & 7;
            cp16(Xb + pl * 9216 + row * 144 + seg * 16,
                 xsrc[pl] + (size_t)row * 524288 + (size_t)s * 1024 + c * 128 + seg * 16);
        }
        asm volatile("cp.async.commit_group;");
    };

    stage(0, Wbuf0, Xbuf0);

    for (int c = 0; c < 8; c++) {
        asm volatile("cp.async.wait_group 0;");
        __syncthreads();
        if (c < 7) stage(c + 1, (c & 1) ? Wbuf0 : Wbuf1, (c & 1) ? Xbuf0 : Xbuf1);
        char* Wb = (c & 1) ? Wbuf1 : Wbuf0;
        char* Xb = (c & 1) ? Xbuf1 : Xbuf0;
#pragma unroll
        for (int kl = 0; kl < 4; kl++) {
            u32 ah[4], al[4];
            int aoff = (m0 + (l & 15)) * 144 + kl * 32 + (l >> 4) * 16;
            ldm4(ah, Xb + aoff);
            ldm4(al, Xb + 9216 + aoff);
            const u32* Wh = (const u32*)Wb;
            const u32* Wl = (const u32*)(Wb + 9216);
#pragma unroll
            for (int nt = 0; nt < 4; nt++) {
                int nrow = nh * 32 + nt * 8 + (l >> 2);
                int wi = nrow * 36 + kl * 8 + (l & 3);
                u32 bh0 = Wh[wi], bh1 = Wh[wi + 4];
                u32 bl0 = Wl[wi], bl1 = Wl[wi + 4];
                mma16816(acc[nt], ah, bh0, bh1);
                mma16816(acc[nt], al, bh0, bh1);
                mma16816(acc[nt], ah, bl0, bl1);
            }
        }
    }

#pragma unroll
    for (int nt = 0; nt < 4; nt++) {
        int col = nb * 64 + nh * 32 + nt * 8 + 2 * (l & 3);
        float2 bi = *(const float2*)&bias[col];
        int b0 = m0 + (l >> 2);
        float2 v0 = make_float2(acc[nt][0] + bi.x, acc[nt][1] + bi.y);
        float2 v1 = make_float2(acc[nt][2] + bi.x, acc[nt][3] + bi.y);
        *(float2*)&g_gi0[(((size_t)d * S + s) * B + b0) * G3 + col] = v0;
        *(float2*)&g_gi0[(((size_t)d * S + s) * B + b0 + 8) * G3 + col] = v1;
    }
}

// ---------------- per-dir grid barrier (64 blocks each) ----------------
__device__ __forceinline__ void grid_bar(int dir, unsigned target) {
    __syncthreads();
    if (threadIdx.x == 0) {
        __threadfence();
        unsigned v = atomicAdd(&g_arrive2[dir], 1u) + 1u;
        if (v == target * 64u) {
            asm volatile("st.release.gpu.u32 [%0], %1;" :: "l"(&g_release2[dir]), "r"(target) : "memory");
        } else {
            unsigned r;
            do {
                asm volatile("ld.acquire.gpu.u32 %0, [%1];" : "=r"(r) : "l"(&g_release2[dir]) : "memory");
            } while (r < target);
        }
    }
    __syncthreads();
}

// ---------------- persistent recurrence kernel (split-bf16 mma) ----------------
// grid 128 (2 dir x 64 hgroups of 8), 512 thr = 16 warps (mtile x4, ksub x4).
// smem: WS 152064 | buf0 36864 (GA/GB/GC alias) | buf1 36864 | GI0S 6144 = 231936 B
// WS rows 264 u32, (k,k+8) u32-pairs interleaved -> conflict-free LDS.64 B-frags.
__global__ void __launch_bounds__(512, 1)
gru_persist(const float* __restrict__ Wih_f, const float* __restrict__ Wih_b,
            const float* __restrict__ Whh_f, const float* __restrict__ Whh_b,
            const float* __restrict__ bih_f, const float* __restrict__ bih_b,
            const float* __restrict__ bhh_f, const float* __restrict__ bhh_b,
            float* __restrict__ out) {
    extern __shared__ char smem[];
    u32*  WS   = (u32*)smem;                     // [(mat*2+plane)*24 + n][264]
    char* buf0 = smem + 152064;                  // 4 planes x [64][72 bf16]
    char* buf1 = smem + 188928;
    float* GI0S = (float*)(smem + 225792);       // [64][24]
    float* GA = (float*)buf0;                    // [64][26]
    float* GB = (float*)(buf0 + 6656);
    float* GC = (float*)(buf0 + 13312);

    const int tid = threadIdx.x;
    const int bid = blockIdx.x;
    const int dir = bid >> 6;
    const int hb  = (bid & 63) * 8;
    const int w = tid >> 5, l = tid & 31;
    const int mtile = w & 3, m0 = mtile * 16, ksub = w >> 2;

    const float* Wih = dir ? Wih_b : Wih_f;
    const float* Whh = dir ? Whh_b : Whh_f;
    const float* bih = dir ? bih_b : bih_f;
    const float* bhh = dir ? bhh_b : bhh_f;
    const float* bhh0 = bhh;
    const float* bi1 = bih + G3;
    const float* bh1 = bhh + G3;

    // ---- one-time weight staging: bf16 hi/lo, (k,k+8)-interleaved u32 pairs ----
    {
        const float* Wmat[3] = { Whh, Wih + (size_t)G3 * D, Whh + (size_t)G3 * H };
#pragma unroll 4
        for (int i = 0; i < 36; i++) {
            int item = tid + 512 * i;            // < 18432 = 3*24*256
            int m3 = item / 6144;
            int rem = item - m3 * 6144;
            int n = rem >> 8;
            int k2 = rem & 255;
            int grow = (n >> 3) * H + hb + (n & 7);
            float2 v = *(const float2*)(Wmat[m3] + (size_t)grow * 512 + 2 * k2);
            bf16 h0, l0, h1, l1;
            split_bf(v.x, h0, l0); split_bf(v.y, h1, l1);
            int j = k2 & 7;
            int col = ((k2 >> 3) << 3) + ((j & 3) << 1) + (j >> 2);
            WS[((m3 * 2 + 0) * 24 + n) * 264 + col] =
                (u32)__bfloat16_as_ushort(h0) | ((u32)__bfloat16_as_ushort(h1) << 16);
            WS[((m3 * 2 + 1) * 24 + n) * 264 + col] =
                (u32)__bfloat16_as_ushort(l0) | ((u32)__bfloat16_as_ushort(l1) << 16);
        }
    }

    const int rowoff = (l >> 2) * 264 + 2 * (l & 3) + ksub * 8;   // per-thread B base

    for (int p = 0; p <= S; p++) {
        const char* Xh = (const char*)g_h0p[p & 1][dir][0];
        const char* Xl = (const char*)g_h0p[p & 1][dir][1];
        const char* Hh = (const char*)g_h1p[(p + 1) & 1][dir][0];
        const char* Hl = (const char*)g_h1p[(p + 1) & 1][dir][1];
        const float* Xf = g_h0f[p & 1][dir];
        const float* Hf = g_h1f[(p + 1) & 1][dir];

        const char* psrc[4] = { Xh, Xl, Hh, Hl };
        auto stage = [&](int c, char* bb) {
            int row = tid >> 3, seg = tid & 7;
#pragma unroll
            for (int pl = 0; pl < 4; pl++) {
                cp16(bb + pl * 9216 + row * 144 + seg * 16,
                     psrc[pl] + row * 1024 + c * 128 + seg * 16);
            }
        };

        // chunk 0 in its own group; gi0 prefetch joins stage(1)'s group
        stage(0, buf0);
        asm volatile("cp.async.commit_group;");
        if (p < S) {
            int tt0 = dir ? (S - 1 - p) : p;
            const float* gi = &g_gi0[((size_t)dir * S + tt0) * B * G3];
            if (tid < 384) {
                int mm = tid / 6, r = tid % 6;
                int gate = r >> 1, half = r & 1;
                cp16(&GI0S[mm * 24 + gate * 8 + half * 4],
                     gi + mm * G3 + gate * H + hb + half * 4);
            }
        }

        float acc[3][3][4];
#pragma unroll
        for (int m3 = 0; m3 < 3; m3++)
#pragma unroll
            for (int nt = 0; nt < 3; nt++)
                acc[m3][nt][0] = acc[m3][nt][1] = acc[m3][nt][2] = acc[m3][nt][3] = 0.f;

        for (int c = 0; c < 8; c++) {
            asm volatile("cp.async.wait_group 0;");
            __syncthreads();
            if (c < 7) {
                stage(c + 1, (c & 1) ? buf0 : buf1);
                asm volatile("cp.async.commit_group;");
            }
            char* bb = (c & 1) ? buf1 : buf0;
            u32 ah[4], al[4], hh4[4], hl4[4];
            int aoff = (m0 + (l & 15)) * 144 + ksub * 32 + (l >> 4) * 16;
            ldm4(ah,  bb + aoff);
            ldm4(al,  bb + 9216  + aoff);
            ldm4(hh4, bb + 18432 + aoff);
            ldm4(hl4, bb + 27648 + aoff);
            const int cb = rowoff + c * 32;
#pragma unroll
            for (int m3 = 0; m3 < 3; m3++) {
                const u32* A  = (m3 == 2) ? hh4 : ah;
                const u32* Al = (m3 == 2) ? hl4 : al;
                const u32* WH = WS + (m3 * 2) * 24 * 264 + cb;
                const u32* WL = WH + 24 * 264;
#pragma unroll
                for (int nt = 0; nt < 3; nt++) {
                    ull wh64 = *(const ull*)(WH + nt * 8 * 264);
                    ull wl64 = *(const ull*)(WL + nt * 8 * 264);
                    u32 bh0 = (u32)wh64, bh1 = (u32)(wh64 >> 32);
                    u32 bl0 = (u32)wl64, bl1 = (u32)(wl64 >> 32);
                    mma16816(acc[m3][nt], A,  bh0, bh1);
                    mma16816(acc[m3][nt], Al, bh0, bh1);
                    mma16816(acc[m3][nt], A,  bl0, bl1);
                }
            }
        }

        // ---- K-split reduction into GA/GB/GC ----
#pragma unroll
        for (int r = 0; r < 4; r++) {
            if (ksub == r) {
#pragma unroll
                for (int m3 = 0; m3 < 3; m3++) {
                    float* G = (m3 == 0) ? GA : (m3 == 1) ? GB : GC;
#pragma unroll
                    for (int nt = 0; nt < 3; nt++) {
                        int col = nt * 8 + 2 * (l & 3);
                        int r0 = m0 + (l >> 2);
                        float2* p0 = (float2*)&G[r0 * 26 + col];
                        float2* p1 = (float2*)&G[(r0 + 8) * 26 + col];
                        float2 v0 = make_float2(acc[m3][nt][0], acc[m3][nt][1]);
                        float2 v1 = make_float2(acc[m3][nt][2], acc[m3][nt][3]);
                        if (r) {
                            float2 o;
                            o = *p0; v0.x += o.x; v0.y += o.y;
                            o = *p1; v1.x += o.x; v1.y += o.y;
                        }
                        *p0 = v0; *p1 = v1;
                    }
                }
            }
            __syncthreads();
        }

        // ---- L0 epilogue: t = p ----
        if (p < S) {
            float* Xnf = g_h0f[(p + 1) & 1][dir];
            bf16* Xnh = g_h0p[(p + 1) & 1][dir][0];
            bf16* Xnl = g_h0p[(p + 1) & 1][dir][1];
            int mm = tid & 63;
            int j  = tid >> 6;
            int row = hb + j;
            float hr = GA[mm * 26 + j]      + bhh0[row];
            float hz = GA[mm * 26 + 8 + j]  + bhh0[H + row];
            float hn = GA[mm * 26 + 16 + j] + bhh0[2 * H + row];
            float rr = sigm(GI0S[mm * 24 + j] + hr);
            float zz = sigm(GI0S[mm * 24 + 8 + j] + hz);
            float nn = tanhf(GI0S[mm * 24 + 16 + j] + rr * hn);
            float hp = __ldcg(&Xf[mm * H + row]);
            float hnew = (1.0f - zz) * nn + zz * hp;
            Xnf[mm * H + row] = hnew;
            bf16 hi, lo; split_bf(hnew, hi, lo);
            Xnh[mm * H + row] = hi;
            Xnl[mm * H + row] = lo;
        }

        // ---- L1 epilogue: t = p-1 ----
        if (p >= 1) {
            int t1 = p - 1;
            int tt = dir ? (S - 1 - t1) : t1;
            float* Hnf = g_h1f[p & 1][dir];
            bf16* Hnh = g_h1p[p & 1][dir][0];
            bf16* Hnl = g_h1p[p & 1][dir][1];
            int mm = tid & 63;
            int j  = tid >> 6;
            int row = hb + j;
            float ir  = GB[mm * 26 + j]      + bi1[row];
            float iz  = GB[mm * 26 + 8 + j]  + bi1[H + row];
            float inn = GB[mm * 26 + 16 + j] + bi1[2 * H + row];
            float hr  = GC[mm * 26 + j]      + bh1[row];
            float hz  = GC[mm * 26 + 8 + j]  + bh1[H + row];
            float hn  = GC[mm * 26 + 16 + j] + bh1[2 * H + row];
            float rr = sigm(ir + hr);
            float zz = sigm(iz + hz);
            float nn = tanhf(inn + rr * hn);
            float hp = __ldcg(&Hf[mm * H + row]);
            float hnew = (1.0f - zz) * nn + zz * hp;
            Hnf[mm * H + row] = hnew;
            bf16 hi, lo; split_bf(hnew, hi, lo);
            Hnh[mm * H + row] = hi;
            Hnl[mm * H + row] = lo;
            out[(size_t)mm * (S * 2 * H) + (size_t)tt * (2 * H) + dir * H + row] = hnew;
        }

        grid_bar(dir, (unsigned)(p + 1));
    }

    // ---- final hidden state copy (own dir only; parity 0) ----
#pragma unroll
    for (int it = 0; it < 2; it++) {
        int local = (bid & 63) * 1024 + it * 512 + tid;   // < 65536 per dir
        int lyr = local >> 15;
        int rem = local & 32767;
        int b = rem >> 9;
        int n = rem & 511;
        float v = lyr ? __ldcg(&g_h1f[0][dir][b * H + n]) : __ldcg(&g_h0f[0][dir][b * H + n]);
        out[(size_t)B * S * 2 * H + ((size_t)lyr * B + b) * (2 * H) + dir * H + n] = v;
    }
}

// ---------------- launch ----------------
extern "C" void kernel_launch(void* const* d_in, const int* in_sizes, int n_in,
                              void* d_out, int out_size) {
    const float* input  = (const float*)d_in[0];
    const float* enc    = (const float*)d_in[1];
    const float* Wih_f  = (const float*)d_in[2];
    const float* Whh_f  = (const float*)d_in[3];
    const float* bih_f  = (const float*)d_in[4];
    const float* bhh_f  = (const float*)d_in[5];
    const float* Wih_b  = (const float*)d_in[6];
    const float* Whh_b  = (const float*)d_in[7];
    const float* bih_b  = (const float*)d_in[8];
    const float* bhh_b  = (const float*)d_in[9];
    float* out = (float*)d_out;

    const int SMEM_G = 73728;
    const int SMEM_P = 231936;
    static int configured = 0;
    if (!configured) {
        cudaFuncSetAttribute(gemm_gi0, cudaFuncAttributeMaxDynamicSharedMemorySize, SMEM_G);
        cudaFuncSetAttribute(gru_persist, cudaFuncAttributeMaxDynamicSharedMemorySize, SMEM_P);
        configured = 1;
    }

    pad_k<<<1, 32>>>();
    init_h<<<512, 256>>>(enc);
    conv_x<<<16384, 256>>>(input);
    conv_w<<<1536, 256>>>(Wih_f, Wih_b);
    gemm_gi0<<<dim3(S, 24, 2), 256, SMEM_G>>>(bih_f, bih_b);
    gru_persist<<<NBLK, 512, SMEM_P>>>(Wih_f, Wih_b, Whh_f, Whh_b,
                                       bih_f, bih_b, bhh_f, bhh_b, out);
}

// round 7
// speedup vs baseline: 3.1418x; 1.3746x over previous
#include <cuda_runtime.h>
#include <cuda_bf16.h>
#include <math.h>

#define S 512
#define B 64
#define H 512
#define D 512
#define G3 1536
#define NBLK 128

typedef unsigned u32;
typedef unsigned long long ull;
typedef __nv_bfloat16 bf16;

// ---------------- device-global scratch (allocation-free rule) ----------------
__device__ float g_gi0[(size_t)2 * S * B * G3];          // fp32 gi0 [dir][t][b][3H]
__device__ bf16  g_xp[2][(size_t)B * S * D];             // input hi/lo planes
__device__ bf16  g_wp[2][2][(size_t)G3 * D];             // Wih layer0 [dir][plane]
__device__ float g_h0f[2][2][B * H];                     // [parity][dir]
__device__ float g_h1f[2][2][B * H];
// h planes in mma-frag layout: u32 idx = kblk*512 + mtile*128 + lane*4 + reg
__device__ u32   g_h0p[2][2][2][16384];                  // [parity][dir][plane]
__device__ u32   g_h1p[2][2][2][16384];
__device__ unsigned g_arrive2[2];
__device__ unsigned g_release2[2];

// ---------------- helpers ----------------
__device__ __forceinline__ void split_bf(float v, bf16& hi, bf16& lo) {
    hi = __float2bfloat16(v);
    lo = __float2bfloat16(v - __bfloat162float(hi));
}
__device__ __forceinline__ float sigm(float x) { return 1.0f / (1.0f + expf(-x)); }

// byte offset of h value (batch b, hidden k) inside a frag-layout plane
__device__ __forceinline__ int frag_byte(int b, int k) {
    int kblk = k >> 4, c = k & 15, mt = b >> 4, r = b & 15;
    int lane = (r & 7) * 4 + ((c & 7) >> 1);
    int reg  = (r >> 3) + 2 * (c >> 3);
    return ((kblk * 512 + mt * 128 + lane * 4 + reg) << 2) + ((c & 1) << 1);
}

__device__ __forceinline__ void mma16816(float* d, const u32* a, u32 b0, u32 b1) {
    asm volatile("mma.sync.aligned.m16n8k16.row.col.f32.bf16.bf16.f32 "
                 "{%0,%1,%2,%3},{%4,%5,%6,%7},{%8,%9},{%0,%1,%2,%3};"
                 : "+f"(d[0]), "+f"(d[1]), "+f"(d[2]), "+f"(d[3])
                 : "r"(a[0]), "r"(a[1]), "r"(a[2]), "r"(a[3]), "r"(b0), "r"(b1));
}
__device__ __forceinline__ void ldm4(u32* r, const void* p) {
    u32 s = (u32)__cvta_generic_to_shared(p);
    asm volatile("ldmatrix.sync.aligned.m8n8.x4.shared.b16 {%0,%1,%2,%3},[%4];"
                 : "=r"(r[0]), "=r"(r[1]), "=r"(r[2]), "=r"(r[3]) : "r"(s));
}
__device__ __forceinline__ void cp16(void* smem_dst, const void* gsrc) {
    u32 s = (u32)__cvta_generic_to_shared(smem_dst);
    asm volatile("cp.async.cg.shared.global [%0], [%1], 16;" :: "r"(s), "l"(gsrc));
}

// ---------------- pad kernel (profile alignment) ----------------
__global__ void pad_k() {}

// ---------------- init: hidden states (fp32 + frag planes) + barrier reset ----------------
__global__ void init_h(const float* __restrict__ enc) {
    if (blockIdx.x == 0 && threadIdx.x < 2) {
        g_arrive2[threadIdx.x] = 0;
        g_release2[threadIdx.x] = 0;
    }
    int idx = blockIdx.x * blockDim.x + threadIdx.x;   // 131072
    int layer = idx >> 16;
    int rem = idx & 65535;
    int dir = rem >> 15;
    int rem2 = rem & 32767;
    int b = rem2 >> 9;
    int n = rem2 & 511;
    float v = enc[(layer * B + b) * (2 * H) + dir * H + n];
    bf16 hi, lo; split_bf(v, hi, lo);
    int off = frag_byte(b, n);
    if (layer == 0) {
        g_h0f[0][dir][b * H + n] = v;
        *(bf16*)((char*)g_h0p[0][dir][0] + off) = hi;
        *(bf16*)((char*)g_h0p[0][dir][1] + off) = lo;
    } else {
        g_h1f[0][dir][b * H + n] = v;
        *(bf16*)((char*)g_h1p[0][dir][0] + off) = hi;
        *(bf16*)((char*)g_h1p[0][dir][1] + off) = lo;
    }
}

// ---------------- conversion kernels ----------------
__global__ void conv_x(const float* __restrict__ x) {
    size_t i = ((size_t)blockIdx.x * 256 + threadIdx.x) * 4;
    float4 v = *(const float4*)&x[i];
    bf16 h0, l0, h1, l1, h2, l2, h3, l3;
    split_bf(v.x, h0, l0); split_bf(v.y, h1, l1);
    split_bf(v.z, h2, l2); split_bf(v.w, h3, l3);
    u32* ph = (u32*)&g_xp[0][i];
    u32* pl = (u32*)&g_xp[1][i];
    ph[0] = (u32)__bfloat16_as_ushort(h0) | ((u32)__bfloat16_as_ushort(h1) << 16);
    ph[1] = (u32)__bfloat16_as_ushort(h2) | ((u32)__bfloat16_as_ushort(h3) << 16);
    pl[0] = (u32)__bfloat16_as_ushort(l0) | ((u32)__bfloat16_as_ushort(l1) << 16);
    pl[1] = (u32)__bfloat16_as_ushort(l2) | ((u32)__bfloat16_as_ushort(l3) << 16);
}
__global__ void conv_w(const float* __restrict__ wf, const float* __restrict__ wb) {
    size_t i = ((size_t)blockIdx.x * 256 + threadIdx.x) * 4;
    int d = i >= (size_t)G3 * D;
    size_t off = d ? i - (size_t)G3 * D : i;
    const float* src = d ? wb : wf;
    float4 v = *(const float4*)&src[off];
    bf16 h0, l0, h1, l1, h2, l2, h3, l3;
    split_bf(v.x, h0, l0); split_bf(v.y, h1, l1);
    split_bf(v.z, h2, l2); split_bf(v.w, h3, l3);
    u32* ph = (u32*)&g_wp[d][0][off];
    u32* pl = (u32*)&g_wp[d][1][off];
    ph[0] = (u32)__bfloat16_as_ushort(h0) | ((u32)__bfloat16_as_ushort(h1) << 16);
    ph[1] = (u32)__bfloat16_as_ushort(h2) | ((u32)__bfloat16_as_ushort(h3) << 16);
    pl[0] = (u32)__bfloat16_as_ushort(l0) | ((u32)__bfloat16_as_ushort(l1) << 16);
    pl[1] = (u32)__bfloat16_as_ushort(l2) | ((u32)__bfloat16_as_ushort(l3) << 16);
}

// ---------------- gi0 = input @ Wih0^T + bih0, split-bf16 mma ----------------
__global__ void __launch_bounds__(256, 3)
gemm_gi0(const float* __restrict__ bf_, const float* __restrict__ bb_) {
    extern __shared__ char sm2[];
    char* Wbuf0 = sm2;
    char* Wbuf1 = sm2 + 18432;
    char* Xbuf0 = sm2 + 36864;
    char* Xbuf1 = sm2 + 55296;

    int s  = blockIdx.x;
    int nb = blockIdx.y;
    int d  = blockIdx.z;
    const float* bias = d ? bb_ : bf_;

    int tid = threadIdx.x;
    int w = tid >> 5, l = tid & 31;
    int mtile = w & 3, m0 = mtile * 16, nh = w >> 2;

    const char* wsrc[2] = { (const char*)&g_wp[d][0][(size_t)(nb * 64) * D],
                            (const char*)&g_wp[d][1][(size_t)(nb * 64) * D] };
    const char* xsrc[2] = { (const char*)&g_xp[0][0], (const char*)&g_xp[1][0] };

    float acc[4][4];
#pragma unroll
    for (int nt = 0; nt < 4; nt++) { acc[nt][0] = acc[nt][1] = acc[nt][2] = acc[nt][3] = 0.f; }

    auto stage = [&](int c, char* Wb, char* Xb) {
#pragma unroll
        for (int i = 0; i < 4; i++) {
            int idx = i * 256 + tid;
            int pl = idx >> 9, row = (idx >> 3) & 63, seg = idx & 7;
            cp16(Wb + pl * 9216 + row * 144 + seg * 16,
                 wsrc[pl] + (size_t)row * 1024 + c * 128 + seg * 16);
        }
#pragma unroll
        for (int i = 0; i < 4; i++) {
            int idx = i * 256 + tid;
            int pl = idx >> 9, row = (idx >> 3) & 63, seg = idx & 7;
            cp16(Xb + pl * 9216 + row * 144 + seg * 16,
                 xsrc[pl] + (size_t)row * 524288 + (size_t)s * 1024 + c * 128 + seg * 16);
        }
        asm volatile("cp.async.commit_group;");
    };

    stage(0, Wbuf0, Xbuf0);

    for (int c = 0; c < 8; c++) {
        asm volatile("cp.async.wait_group 0;");
        __syncthreads();
        if (c < 7) stage(c + 1, (c & 1) ? Wbuf0 : Wbuf1, (c & 1) ? Xbuf0 : Xbuf1);
        char* Wb = (c & 1) ? Wbuf1 : Wbuf0;
        char* Xb = (c & 1) ? Xbuf1 : Xbuf0;
#pragma unroll
        for (int kl = 0; kl < 4; kl++) {
            u32 ah[4], al[4];
            int aoff = (m0 + (l & 15)) * 144 + kl * 32 + (l >> 4) * 16;
            ldm4(ah, Xb + aoff);
            ldm4(al, Xb + 9216 + aoff);
            const u32* Wh = (const u32*)Wb;
            const u32* Wl = (const u32*)(Wb + 9216);
#pragma unroll
            for (int nt = 0; nt < 4; nt++) {
                int nrow = nh * 32 + nt * 8 + (l >> 2);
                int wi = nrow * 36 + kl * 8 + (l & 3);
                u32 bh0 = Wh[wi], bh1 = Wh[wi + 4];
                u32 bl0 = Wl[wi], bl1 = Wl[wi + 4];
                mma16816(acc[nt], ah, bh0, bh1);
                mma16816(acc[nt], al, bh0, bh1);
                mma16816(acc[nt], ah, bl0, bl1);
            }
        }
    }

#pragma unroll
    for (int nt = 0; nt < 4; nt++) {
        int col = nb * 64 + nh * 32 + nt * 8 + 2 * (l & 3);
        float2 bi = *(const float2*)&bias[col];
        int b0 = m0 + (l >> 2);
        float2 v0 = make_float2(acc[nt][0] + bi.x, acc[nt][1] + bi.y);
        float2 v1 = make_float2(acc[nt][2] + bi.x, acc[nt][3] + bi.y);
        *(float2*)&g_gi0[(((size_t)d * S + s) * B + b0) * G3 + col] = v0;
        *(float2*)&g_gi0[(((size_t)d * S + s) * B + b0 + 8) * G3 + col] = v1;
    }
}

// ---------------- per-dir grid barrier ----------------
__device__ __forceinline__ void grid_bar(int dir, unsigned target) {
    __syncthreads();
    if (threadIdx.x == 0) {
        __threadfence();
        unsigned v = atomicAdd(&g_arrive2[dir], 1u) + 1u;
        if (v == target * 64u) {
            asm volatile("st.release.gpu.u32 [%0], %1;" :: "l"(&g_release2[dir]), "r"(target) : "memory");
        } else {
            unsigned r;
            do {
                asm volatile("ld.acquire.gpu.u32 %0, [%1];" : "=r"(r) : "l"(&g_release2[dir]) : "memory");
            } while (r < target);
        }
    }
    __syncthreads();
}

// ---------------- persistent recurrence kernel ----------------
// grid 128 (2 dir x 64 hgroups of 8), 512 thr = 16 warps (mtile x4, ksub x4).
// A-fragments loaded straight from frag-layout global planes (no smem staging).
// smem: WS 152064 | GA/GB/GC 19968 | GI0S 6144 = 178176 B
__global__ void __launch_bounds__(512, 1)
gru_persist(const float* __restrict__ Wih_f, const float* __restrict__ Wih_b,
            const float* __restrict__ Whh_f, const float* __restrict__ Whh_b,
            const float* __restrict__ bih_f, const float* __restrict__ bih_b,
            const float* __restrict__ bhh_f, const float* __restrict__ bhh_b,
            float* __restrict__ out) {
    extern __shared__ char smem[];
    u32*  WS   = (u32*)smem;                     // [(mat*2+plane)*24 + n][264]
    float* GA  = (float*)(smem + 152064);        // [64][26]
    float* GB  = (float*)(smem + 158720);
    float* GC  = (float*)(smem + 165376);
    float* GI0S = (float*)(smem + 172032);       // [64][24]

    const int tid = threadIdx.x;
    const int bid = blockIdx.x;
    const int dir = bid >> 6;
    const int hb  = (bid & 63) * 8;
    const int w = tid >> 5, l = tid & 31;
    const int mtile = w & 3, m0 = mtile * 16, ksub = w >> 2;

    const float* Wih = dir ? Wih_b : Wih_f;
    const float* Whh = dir ? Whh_b : Whh_f;
    const float* bih = dir ? bih_b : bih_f;
    const float* bhh = dir ? bhh_b : bhh_f;
    const float* bhh0 = bhh;
    const float* bi1 = bih + G3;
    const float* bh1 = bhh + G3;

    // ---- one-time weight staging: bf16 hi/lo, (k,k+8)-interleaved u32 pairs ----
    {
        const float* Wmat[3] = { Whh, Wih + (size_t)G3 * D, Whh + (size_t)G3 * H };
#pragma unroll 4
        for (int i = 0; i < 36; i++) {
            int item = tid + 512 * i;            // < 18432
            int m3 = item / 6144;
            int rem = item - m3 * 6144;
            int n = rem >> 8;
            int k2 = rem & 255;
            int grow = (n >> 3) * H + hb + (n & 7);
            float2 v = *(const float2*)(Wmat[m3] + (size_t)grow * 512 + 2 * k2);
            bf16 h0, l0, h1, l1;
            split_bf(v.x, h0, l0); split_bf(v.y, h1, l1);
            int j = k2 & 7;
            int col = ((k2 >> 3) << 3) + ((j & 3) << 1) + (j >> 2);
            WS[((m3 * 2 + 0) * 24 + n) * 264 + col] =
                (u32)__bfloat16_as_ushort(h0) | ((u32)__bfloat16_as_ushort(h1) << 16);
            WS[((m3 * 2 + 1) * 24 + n) * 264 + col] =
                (u32)__bfloat16_as_ushort(l0) | ((u32)__bfloat16_as_ushort(l1) << 16);
        }
    }

    const int rowoff = (l >> 2) * 264 + 2 * (l & 3) + ksub * 8;
    const int fbase  = mtile * 128 + l * 4;

    for (int p = 0; p <= S; p++) {
        const u32* Apl[4] = { g_h0p[p & 1][dir][0], g_h0p[p & 1][dir][1],
                              g_h1p[(p + 1) & 1][dir][0], g_h1p[(p + 1) & 1][dir][1] };
        const float* Xf = g_h0f[p & 1][dir];
        const float* Hf = g_h1f[(p + 1) & 1][dir];

        // gi0 prefetch (used in L0 epilogue)
        if (p < S) {
            int tt0 = dir ? (S - 1 - p) : p;
            const float* gi = &g_gi0[((size_t)dir * S + tt0) * B * G3];
            if (tid < 384) {
                int mm = tid / 6, r = tid % 6;
                int gate = r >> 1, half = r & 1;
                cp16(&GI0S[mm * 24 + gate * 8 + half * 4],
                     gi + mm * G3 + gate * H + hb + half * 4);
            }
            asm volatile("cp.async.commit_group;");
        }

        float acc[3][3][4];
#pragma unroll
        for (int m3 = 0; m3 < 3; m3++)
#pragma unroll
            for (int nt = 0; nt < 3; nt++)
                acc[m3][nt][0] = acc[m3][nt][1] = acc[m3][nt][2] = acc[m3][nt][3] = 0.f;

        u32 f0[4][4], f1[4][4];
        {
            int idx = ksub * 512 + fbase;
#pragma unroll
            for (int pl = 0; pl < 4; pl++) {
                uint4 v = __ldcg((const uint4*)(Apl[pl] + idx));
                f0[pl][0] = v.x; f0[pl][1] = v.y; f0[pl][2] = v.z; f0[pl][3] = v.w;
            }
        }

#pragma unroll
        for (int c = 0; c < 8; c++) {
            if (c < 7) {
                int idx = ((c + 1) * 4 + ksub) * 512 + fbase;
                u32 (*Fn)[4] = (c & 1) ? f0 : f1;
#pragma unroll
                for (int pl = 0; pl < 4; pl++) {
                    uint4 v = __ldcg((const uint4*)(Apl[pl] + idx));
                    Fn[pl][0] = v.x; Fn[pl][1] = v.y; Fn[pl][2] = v.z; Fn[pl][3] = v.w;
                }
            }
            u32 (*Af)[4] = (c & 1) ? f1 : f0;
            const int cb = rowoff + c * 32;
#pragma unroll
            for (int m3 = 0; m3 < 3; m3++) {
                const u32* Ahi = (m3 == 2) ? Af[2] : Af[0];
                const u32* Alo = (m3 == 2) ? Af[3] : Af[1];
                const u32* WH = WS + (m3 * 2) * 24 * 264 + cb;
                const u32* WL = WH + 24 * 264;
#pragma unroll
                for (int nt = 0; nt < 3; nt++) {
                    ull wh64 = *(const ull*)(WH + nt * 8 * 264);
                    ull wl64 = *(const ull*)(WL + nt * 8 * 264);
                    u32 bh0 = (u32)wh64, bh1 = (u32)(wh64 >> 32);
                    u32 bl0 = (u32)wl64, bl1 = (u32)(wl64 >> 32);
                    mma16816(acc[m3][nt], Ahi, bh0, bh1);
                    mma16816(acc[m3][nt], Alo, bh0, bh1);
                    mma16816(acc[m3][nt], Ahi, bl0, bl1);
                }
            }
        }

        // ---- K-split reduction into GA/GB/GC ----
        __syncthreads();    // protect G buffers from previous phase's epilogue reads
#pragma unroll
        for (int r = 0; r < 4; r++) {
            if (ksub == r) {
#pragma unroll
                for (int m3 = 0; m3 < 3; m3++) {
                    float* G = (m3 == 0) ? GA : (m3 == 1) ? GB : GC;
#pragma unroll
                    for (int nt = 0; nt < 3; nt++) {
                        int col = nt * 8 + 2 * (l & 3);
                        int r0 = m0 + (l >> 2);
                        float2* p0 = (float2*)&G[r0 * 26 + col];
                        float2* p1 = (float2*)&G[(r0 + 8) * 26 + col];
                        float2 v0 = make_float2(acc[m3][nt][0], acc[m3][nt][1]);
                        float2 v1 = make_float2(acc[m3][nt][2], acc[m3][nt][3]);
                        if (r) {
                            float2 o;
                            o = *p0; v0.x += o.x; v0.y += o.y;
                            o = *p1; v1.x += o.x; v1.y += o.y;
                        }
                        *p0 = v0; *p1 = v1;
                    }
                }
            }
            __syncthreads();
        }
        asm volatile("cp.async.wait_group 0;");

        // ---- L0 epilogue: t = p ----
        if (p < S) {
            float* Xnf = g_h0f[(p + 1) & 1][dir];
            char* Xnh = (char*)g_h0p[(p + 1) & 1][dir][0];
            char* Xnl = (char*)g_h0p[(p + 1) & 1][dir][1];
            int mm = tid & 63;
            int j  = tid >> 6;
            int row = hb + j;
            float hr = GA[mm * 26 + j]      + bhh0[row];
            float hz = GA[mm * 26 + 8 + j]  + bhh0[H + row];
            float hn = GA[mm * 26 + 16 + j] + bhh0[2 * H + row];
            float rr = sigm(GI0S[mm * 24 + j] + hr);
            float zz = sigm(GI0S[mm * 24 + 8 + j] + hz);
            float nn = tanhf(GI0S[mm * 24 + 16 + j] + rr * hn);
            float hp = __ldcg(&Xf[mm * H + row]);
            float hnew = (1.0f - zz) * nn + zz * hp;
            Xnf[mm * H + row] = hnew;
            bf16 hi, lo; split_bf(hnew, hi, lo);
            int off = frag_byte(mm, row);
            *(bf16*)(Xnh + off) = hi;
            *(bf16*)(Xnl + off) = lo;
        }

        // ---- L1 epilogue: t = p-1 ----
        if (p >= 1) {
            int t1 = p - 1;
            int tt = dir ? (S - 1 - t1) : t1;
            float* Hnf = g_h1f[p & 1][dir];
            char* Hnh = (char*)g_h1p[p & 1][dir][0];
            char* Hnl = (char*)g_h1p[p & 1][dir][1];
            int mm = tid & 63;
            int j  = tid >> 6;
            int row = hb + j;
            float ir  = GB[mm * 26 + j]      + bi1[row];
            float iz  = GB[mm * 26 + 8 + j]  + bi1[H + row];
            float inn = GB[mm * 26 + 16 + j] + bi1[2 * H + row];
            float hr  = GC[mm * 26 + j]      + bh1[row];
            float hz  = GC[mm * 26 + 8 + j]  + bh1[H + row];
            float hn  = GC[mm * 26 + 16 + j] + bh1[2 * H + row];
            float rr = sigm(ir + hr);
            float zz = sigm(iz + hz);
            float nn = tanhf(inn + rr * hn);
            float hp = __ldcg(&Hf[mm * H + row]);
            float hnew = (1.0f - zz) * nn + zz * hp;
            Hnf[mm * H + row] = hnew;
            bf16 hi, lo; split_bf(hnew, hi, lo);
            int off = frag_byte(mm, row);
            *(bf16*)(Hnh + off) = hi;
            *(bf16*)(Hnl + off) = lo;
            out[(size_t)mm * (S * 2 * H) + (size_t)tt * (2 * H) + dir * H + row] = hnew;
        }

        grid_bar(dir, (unsigned)(p + 1));
    }

    // ---- final hidden state copy (own dir; parity 0) ----
#pragma unroll
    for (int it = 0; it < 2; it++) {
        int local = (bid & 63) * 1024 + it * 512 + tid;   // < 65536 per dir
        int lyr = local >> 15;
        int rem = local & 32767;
        int b = rem >> 9;
        int n = rem & 511;
        float v = lyr ? __ldcg(&g_h1f[0][dir][b * H + n]) : __ldcg(&g_h0f[0][dir][b * H + n]);
        out[(size_t)B * S * 2 * H + ((size_t)lyr * B + b) * (2 * H) + dir * H + n] = v;
    }
}

// ---------------- launch ----------------
extern "C" void kernel_launch(void* const* d_in, const int* in_sizes, int n_in,
                              void* d_out, int out_size) {
    const float* input  = (const float*)d_in[0];
    const float* enc    = (const float*)d_in[1];
    const float* Wih_f  = (const float*)d_in[2];
    const float* Whh_f  = (const float*)d_in[3];
    const float* bih_f  = (const float*)d_in[4];
    const float* bhh_f  = (const float*)d_in[5];
    const float* Wih_b  = (const float*)d_in[6];
    const float* Whh_b  = (const float*)d_in[7];
    const float* bih_b  = (const float*)d_in[8];
    const float* bhh_b  = (const float*)d_in[9];
    float* out = (float*)d_out;

    const int SMEM_G = 73728;
    const int SMEM_P = 178176;
    static int configured = 0;
    if (!configured) {
        cudaFuncSetAttribute(gemm_gi0, cudaFuncAttributeMaxDynamicSharedMemorySize, SMEM_G);
        cudaFuncSetAttribute(gru_persist, cudaFuncAttributeMaxDynamicSharedMemorySize, SMEM_P);
        configured = 1;
    }

    pad_k<<<1, 32>>>();
    init_h<<<512, 256>>>(enc);
    conv_x<<<16384, 256>>>(input);
    conv_w<<<1536, 256>>>(Wih_f, Wih_b);
    gemm_gi0<<<dim3(S, 24, 2), 256, SMEM_G>>>(bih_f, bih_b);
    gru_persist<<<NBLK, 512, SMEM_P>>>(Wih_f, Wih_b, Whh_f, Whh_b,
                                       bih_f, bih_b, bhh_f, bhh_b, out);
}